// round 4
// baseline (speedup 1.0000x reference)
#include <cuda_runtime.h>
#include <cstdint>

#define BB 8
#define CC 96
#define HH 512
#define WW 96
#define HWX (HH*WW)     // 49152
#define OC  (3*CC)      // 288
#define SS  100         // smem row stride (floats); rows 400B -> 16B aligned

typedef unsigned long long u64;

__device__ __align__(16) float g_WT[CC*OC];   // W'^T: [c][o], BN folded
__device__ float g_bias[OC];

struct __align__(16) U64x2 { u64 lo, hi; };

// ---------------- packed f32x2 helpers ----------------
__device__ __forceinline__ u64 ffma2(u64 a, u64 b, u64 c){
    u64 d; asm("fma.rn.f32x2 %0, %1, %2, %3;" : "=l"(d) : "l"(a), "l"(b), "l"(c)); return d;
}
__device__ __forceinline__ u64 add2(u64 a, u64 b){
    u64 d; asm("add.rn.f32x2 %0, %1, %2;" : "=l"(d) : "l"(a), "l"(b)); return d;
}
__device__ __forceinline__ u64 pack2(float x){
    u64 d; asm("mov.b64 %0, {%1, %1};" : "=l"(d) : "f"(x)); return d;
}

// ---------------- prep: fold BN into QKV weights ----------------
__global__ void prep_kernel(const float* __restrict__ qkv_w, const float* __restrict__ qkv_b,
                            const float* __restrict__ gam, const float* __restrict__ bet,
                            const float* __restrict__ mn,  const float* __restrict__ vr){
    int o = blockIdx.x;
    int c = threadIdx.x;
    __shared__ float red[CC];
    float inv   = gam[c] * rsqrtf(vr[c] + 1e-5f);
    float shift = bet[c] - mn[c]*inv;
    float wv = qkv_w[o*CC + c];
    g_WT[c*OC + o] = wv * inv;
    red[c] = wv * shift;
    __syncthreads();
    if (c < 32){
        float s = red[c] + red[c+32] + red[c+64];
        #pragma unroll
        for (int off = 16; off; off >>= 1) s += __shfl_down_sync(0xffffffffu, s, off);
        if (c == 0) g_bias[o] = s + qkv_b[o];
    }
}

// ---------------- shared GEMM inner loop ----------------
// acc[i][j]: rows aB[c*SS + i] (i<3), col-pairs bB[c*SS + 2j] (j<6)
// aB pre-offset by 3*ty, bB pre-offset by 12*tx. Reduction over c = 0..95.
__device__ __forceinline__ void gemm96(const float* __restrict__ aB,
                                       const float* __restrict__ bB,
                                       u64 acc[3][6]){
    #pragma unroll 4
    for (int c = 0; c < CC; ++c){
        const float* ar = aB + c*SS;
        const float* br = bB + c*SS;
        U64x2 b0 = *(const U64x2*)(br);       // LDS.128, conflict-free
        U64x2 b1 = *(const U64x2*)(br + 4);
        U64x2 b2 = *(const U64x2*)(br + 8);
        u64 bv[6] = { b0.lo, b0.hi, b1.lo, b1.hi, b2.lo, b2.hi };
        u64 A[3]  = { pack2(ar[0]), pack2(ar[1]), pack2(ar[2]) };
        #pragma unroll
        for (int i = 0; i < 3; ++i)
            #pragma unroll
            for (int j = 0; j < 6; ++j)
                acc[i][j] = ffma2(A[i], bv[j], acc[i][j]);
    }
}

__device__ __forceinline__ void store_tile(float* dst, u64 acc[3][6]){
    // dst pre-offset by (3*ty)*SS + 12*tx
    #pragma unroll
    for (int i = 0; i < 3; ++i)
        #pragma unroll
        for (int j = 0; j < 6; ++j)
            *(u64*)(dst + i*SS + 2*j) = acc[i][j];
}

// ---------------- fused attention kernel ----------------
// one CTA per (b,h). 256 threads: tx = t&7 (12 cols), ty = t>>3 (3 rows)
__global__ __launch_bounds__(256) void attn_kernel(const float* __restrict__ x,
                                                   float* __restrict__ out){
    extern __shared__ float sm[];
    float* xs = sm;              // x tile [c][w] (kept pristine for residual)
    float* ws = sm + 1*CC*SS;    // weights block, then score [q][k]
    float* qs = sm + 2*CC*SS;    // q [o][w]; later attn^T [k][q]
    float* ks = sm + 3*CC*SS;    // k [o][w]
    float* vt = sm + 4*CC*SS;    // v transposed [w][o]

    const int t  = threadIdx.x;
    const int tx = t & 7;
    const int ty = t >> 3;       // 0..31
    const int aOff = 3*ty;       // row offset
    const int bOff = 12*tx;      // col offset
    const int bh = blockIdx.x;
    const int b  = bh >> 9;      // H = 512
    const int h  = bh & 511;
    const size_t base = (size_t)b*CC*HWX + (size_t)h*WW;

    // ---- load x tile (coalesced float4) ----
    for (int idx = t; idx < CC*24; idx += 256){
        int c = idx/24, j = idx%24;
        *(float4*)&xs[c*SS + 4*j] = *(const float4*)(x + base + (size_t)c*HWX + 4*j);
    }

    u64 acc[3][6];

    // ---- QKV: 3 passes. p=0: q[o][w], p=1: k[o][w], p=2: v^T[w][o] ----
    for (int p = 0; p < 3; ++p){
        if (p) __syncthreads();                 // done reading ws from prior pass
        for (int idx = t; idx < CC*24; idx += 256){
            int c = idx/24, j = idx%24;
            *(float4*)&ws[c*SS + 4*j] = *(const float4*)&g_WT[c*OC + p*CC + 4*j];
        }
        __syncthreads();

        if (p < 2){
            // rows = o (weights), cols = w (x)
            #pragma unroll
            for (int i = 0; i < 3; ++i){
                u64 b2 = pack2(g_bias[p*CC + aOff + i]);
                #pragma unroll
                for (int j = 0; j < 6; ++j) acc[i][j] = b2;
            }
            gemm96(ws + aOff, xs + bOff, acc);
            store_tile(((p == 0) ? qs : ks) + aOff*SS + bOff, acc);
        } else {
            // v with swapped roles: rows = w (x), cols = o (weights) -> v^T
            #pragma unroll
            for (int j = 0; j < 6; ++j){
                u64 bj = *(const u64*)&g_bias[2*CC + bOff + 2*j];
                #pragma unroll
                for (int i = 0; i < 3; ++i) acc[i][j] = bj;
            }
            gemm96(xs + aOff, ws + bOff, acc);
            store_tile(vt + aOff*SS + bOff, acc);
        }
    }
    __syncthreads();

    // ---- score[q][k] = sum_c q[c][q] * k[c][k] -> ws ----
    #pragma unroll
    for (int i = 0; i < 3; ++i)
        #pragma unroll
        for (int j = 0; j < 6; ++j) acc[i][j] = 0ull;
    gemm96(qs + aOff, ks + bOff, acc);
    store_tile(ws + aOff*SS + bOff, acc);
    __syncthreads();

    // ---- softmax over k; write TRANSPOSED attn^T[k][q] into qs ----
    {
        int warp = t >> 5, lane = t & 31;
        for (int r = warp*12; r < warp*12 + 12; ++r){
            const float* row = &ws[r*SS];
            float v0 = row[lane], v1 = row[lane+32], v2 = row[lane+64];
            float m = fmaxf(v0, fmaxf(v1, v2));
            #pragma unroll
            for (int o2 = 16; o2; o2 >>= 1) m = fmaxf(m, __shfl_xor_sync(0xffffffffu, m, o2));
            float e0 = __expf(v0 - m), e1 = __expf(v1 - m), e2 = __expf(v2 - m);
            float s = e0 + e1 + e2;
            #pragma unroll
            for (int o2 = 16; o2; o2 >>= 1) s += __shfl_xor_sync(0xffffffffu, s, o2);
            float inv = 1.0f / s;
            qs[(lane   )*SS + r] = e0*inv;
            qs[(lane+32)*SS + r] = e1*inv;
            qs[(lane+64)*SS + r] = e2*inv;
        }
    }
    __syncthreads();

    // ---- AV: out[c][q] = sum_k v^T[k][c] * attn^T[k][q]; fuse residual + STG ----
    #pragma unroll
    for (int i = 0; i < 3; ++i)
        #pragma unroll
        for (int j = 0; j < 6; ++j) acc[i][j] = 0ull;
    gemm96(vt + aOff, qs + bOff, acc);

    #pragma unroll
    for (int i = 0; i < 3; ++i){
        int c = aOff + i;
        const float* xr = &xs[c*SS + bOff];
        float* orow = out + base + (size_t)c*HWX + bOff;
        #pragma unroll
        for (int j = 0; j < 6; ++j){
            u64 r = *(const u64*)(xr + 2*j);
            *(u64*)(orow + 2*j) = add2(acc[i][j], r);
        }
    }
}

extern "C" void kernel_launch(void* const* d_in, const int* in_sizes, int n_in,
                              void* d_out, int out_size){
    const float* x     = (const float*)d_in[0];
    const float* gam   = (const float*)d_in[1];
    const float* bet   = (const float*)d_in[2];
    const float* mn    = (const float*)d_in[3];
    const float* vr    = (const float*)d_in[4];
    const float* qkv_w = (const float*)d_in[5];
    const float* qkv_b = (const float*)d_in[6];
    float* out = (float*)d_out;

    cudaFuncSetAttribute(attn_kernel, cudaFuncAttributeMaxDynamicSharedMemorySize, CC*SS*5*sizeof(float));

    prep_kernel<<<OC, CC>>>(qkv_w, qkv_b, gam, bet, mn, vr);
    attn_kernel<<<BB*HH, 256, CC*SS*5*sizeof(float)>>>(x, out);
}

// round 6
// speedup vs baseline: 1.1378x; 1.1378x over previous
#include <cuda_runtime.h>
#include <cstdint>

#define BB 8
#define CC 96
#define HH 512
#define WW 96
#define HWX (HH*WW)     // 49152
#define OC  (3*CC)      // 288
#define SS  100         // smem row stride (floats); rows 400B -> 16B aligned

typedef unsigned long long u64;

__device__ __align__(16) float g_WT[CC*OC];   // W'^T: [c][o], BN folded
__device__ float g_bias[OC];

struct __align__(16) U64x2 { u64 lo, hi; };

// ---------------- packed f32x2 helpers ----------------
__device__ __forceinline__ u64 ffma2(u64 a, u64 b, u64 c){
    u64 d; asm("fma.rn.f32x2 %0, %1, %2, %3;" : "=l"(d) : "l"(a), "l"(b), "l"(c)); return d;
}
__device__ __forceinline__ u64 add2(u64 a, u64 b){
    u64 d; asm("add.rn.f32x2 %0, %1, %2;" : "=l"(d) : "l"(a), "l"(b)); return d;
}
__device__ __forceinline__ u64 pack2(float x){
    u64 d; asm("mov.b64 %0, {%1, %1};" : "=l"(d) : "f"(x)); return d;
}

// ---------------- prep: fold BN into QKV weights ----------------
__global__ void prep_kernel(const float* __restrict__ qkv_w, const float* __restrict__ qkv_b,
                            const float* __restrict__ gam, const float* __restrict__ bet,
                            const float* __restrict__ mn,  const float* __restrict__ vr){
    int o = blockIdx.x;
    int c = threadIdx.x;
    __shared__ float red[CC];
    float inv   = gam[c] * rsqrtf(vr[c] + 1e-5f);
    float shift = bet[c] - mn[c]*inv;
    float wv = qkv_w[o*CC + c];
    g_WT[c*OC + o] = wv * inv;
    red[c] = wv * shift;
    __syncthreads();
    if (c < 32){
        float s = red[c] + red[c+32] + red[c+64];
        #pragma unroll
        for (int off = 16; off; off >>= 1) s += __shfl_down_sync(0xffffffffu, s, off);
        if (c == 0) g_bias[o] = s + qkv_b[o];
    }
}

// ---------------- shared GEMM inner loop ----------------
// Thread tile: rows aB[c*SS + i] (i<3, per-lane), col-pairs bB[c*SS + 2j] (j<6, per-warp).
// aB pre-offset by 3*lane (conflict-free LDS.32, stride 3 coprime 32).
// bB pre-offset by 12*warp -> WARP-UNIFORM address: LDS.128 broadcast, ~1 wavefront.
__device__ __forceinline__ void gemm96(const float* __restrict__ aB,
                                       const float* __restrict__ bB,
                                       u64 acc[3][6]){
    #pragma unroll 4
    for (int c = 0; c < CC; ++c){
        const float* ar = aB + c*SS;
        const float* br = bB + c*SS;
        U64x2 b0 = *(const U64x2*)(br);       // broadcast LDS.128
        U64x2 b1 = *(const U64x2*)(br + 4);
        U64x2 b2 = *(const U64x2*)(br + 8);
        u64 bv[6] = { b0.lo, b0.hi, b1.lo, b1.hi, b2.lo, b2.hi };
        u64 A[3]  = { pack2(ar[0]), pack2(ar[1]), pack2(ar[2]) };
        #pragma unroll
        for (int i = 0; i < 3; ++i)
            #pragma unroll
            for (int j = 0; j < 6; ++j)
                acc[i][j] = ffma2(A[i], bv[j], acc[i][j]);
    }
}

__device__ __forceinline__ void store_tile(float* dst, u64 acc[3][6]){
    // dst pre-offset by (3*lane)*SS + 12*warp
    #pragma unroll
    for (int i = 0; i < 3; ++i)
        #pragma unroll
        for (int j = 0; j < 6; ++j)
            *(u64*)(dst + i*SS + 2*j) = acc[i][j];
}

// ---------------- fused attention kernel ----------------
// one CTA per (b,h). 256 threads = 8 warps.
// warp owns 12 cols (bOff = 12*warp), lane owns 3 rows (aOff = 3*lane).
__global__ __launch_bounds__(256) void attn_kernel(const float* __restrict__ x,
                                                   float* __restrict__ out){
    extern __shared__ float sm[];
    float* xs = sm;              // x tile [c][w] (pristine, for residual)
    float* ws = sm + 1*CC*SS;    // weights block -> score [q][k] -> final out [c][w]
    float* qs = sm + 2*CC*SS;    // q [o][w]; later attn^T [k][q]
    float* ks = sm + 3*CC*SS;    // k [o][w]
    float* vt = sm + 4*CC*SS;    // v transposed [w][o]

    const int t    = threadIdx.x;
    const int lane = t & 31;
    const int warp = t >> 5;
    const int aOff = 3*lane;     // row offset (per-lane)
    const int bOff = 12*warp;    // col offset (per-warp, uniform)
    const int bh = blockIdx.x;
    const int b  = bh >> 9;      // H = 512
    const int h  = bh & 511;
    const size_t base = (size_t)b*CC*HWX + (size_t)h*WW;

    // ---- load x tile (coalesced float4) ----
    for (int idx = t; idx < CC*24; idx += 256){
        int c = idx/24, j = idx%24;
        *(float4*)&xs[c*SS + 4*j] = *(const float4*)(x + base + (size_t)c*HWX + 4*j);
    }

    u64 acc[3][6];

    // ---- QKV: 3 passes. p=0: q[o][w], p=1: k[o][w], p=2: v^T[w][o] ----
    for (int p = 0; p < 3; ++p){
        if (p) __syncthreads();                 // done reading ws from prior pass
        for (int idx = t; idx < CC*24; idx += 256){
            int c = idx/24, j = idx%24;
            *(float4*)&ws[c*SS + 4*j] = *(const float4*)&g_WT[c*OC + p*CC + 4*j];
        }
        __syncthreads();

        if (p < 2){
            // rows = o (weights), cols = w (x)
            #pragma unroll
            for (int i = 0; i < 3; ++i){
                u64 b2 = pack2(g_bias[p*CC + aOff + i]);
                #pragma unroll
                for (int j = 0; j < 6; ++j) acc[i][j] = b2;
            }
            gemm96(ws + aOff, xs + bOff, acc);
            store_tile(((p == 0) ? qs : ks) + aOff*SS + bOff, acc);
        } else {
            // v with swapped roles: rows = w (x), cols = o (weights) -> v^T
            #pragma unroll
            for (int j = 0; j < 6; ++j){
                u64 bj = *(const u64*)&g_bias[2*CC + bOff + 2*j];
                #pragma unroll
                for (int i = 0; i < 3; ++i) acc[i][j] = bj;
            }
            gemm96(xs + aOff, ws + bOff, acc);
            store_tile(vt + aOff*SS + bOff, acc);
        }
    }
    __syncthreads();

    // ---- score[q][k] = sum_c q[c][q] * k[c][k] -> ws ----
    #pragma unroll
    for (int i = 0; i < 3; ++i)
        #pragma unroll
        for (int j = 0; j < 6; ++j) acc[i][j] = 0ull;
    gemm96(qs + aOff, ks + bOff, acc);
    store_tile(ws + aOff*SS + bOff, acc);
    __syncthreads();

    // ---- softmax over k; write TRANSPOSED attn^T[k][q] into qs ----
    {
        for (int r = warp*12; r < warp*12 + 12; ++r){
            const float* row = &ws[r*SS];
            float v0 = row[lane], v1 = row[lane+32], v2 = row[lane+64];
            float m = fmaxf(v0, fmaxf(v1, v2));
            #pragma unroll
            for (int o2 = 16; o2; o2 >>= 1) m = fmaxf(m, __shfl_xor_sync(0xffffffffu, m, o2));
            float e0 = __expf(v0 - m), e1 = __expf(v1 - m), e2 = __expf(v2 - m);
            float s = e0 + e1 + e2;
            #pragma unroll
            for (int o2 = 16; o2; o2 >>= 1) s += __shfl_xor_sync(0xffffffffu, s, o2);
            float inv = 1.0f / s;
            qs[(lane   )*SS + r] = e0*inv;
            qs[(lane+32)*SS + r] = e1*inv;
            qs[(lane+64)*SS + r] = e2*inv;
        }
    }
    __syncthreads();

    // ---- AV: out[c][q] = sum_k v^T[k][c] * attn^T[k][q] ----
    #pragma unroll
    for (int i = 0; i < 3; ++i)
        #pragma unroll
        for (int j = 0; j < 6; ++j) acc[i][j] = 0ull;
    gemm96(vt + aOff, qs + bOff, acc);

    // residual add into ws ([c][w] layout), then coalesced writeout
    #pragma unroll
    for (int i = 0; i < 3; ++i){
        int c = aOff + i;
        const float* xr = &xs[c*SS + bOff];
        float* wr = &ws[c*SS + bOff];
        #pragma unroll
        for (int j = 0; j < 6; ++j){
            u64 r = *(const u64*)(xr + 2*j);
            *(u64*)(wr + 2*j) = add2(acc[i][j], r);
        }
    }
    __syncthreads();

    for (int idx = t; idx < CC*24; idx += 256){
        int c = idx/24, j = idx%24;
        *(float4*)(out + base + (size_t)c*HWX + 4*j) = *(const float4*)&ws[c*SS + 4*j];
    }
}

extern "C" void kernel_launch(void* const* d_in, const int* in_sizes, int n_in,
                              void* d_out, int out_size){
    const float* x     = (const float*)d_in[0];
    const float* gam   = (const float*)d_in[1];
    const float* bet   = (const float*)d_in[2];
    const float* mn    = (const float*)d_in[3];
    const float* vr    = (const float*)d_in[4];
    const float* qkv_w = (const float*)d_in[5];
    const float* qkv_b = (const float*)d_in[6];
    float* out = (float*)d_out;

    cudaFuncSetAttribute(attn_kernel, cudaFuncAttributeMaxDynamicSharedMemorySize, CC*SS*5*sizeof(float));

    prep_kernel<<<OC, CC>>>(qkv_w, qkv_b, gam, bet, mn, vr);
    attn_kernel<<<BB*HH, 256, CC*SS*5*sizeof(float)>>>(x, out);
}

// round 8
// speedup vs baseline: 1.2303x; 1.0813x over previous
#include <cuda_runtime.h>
#include <cstdint>

#define BB 8
#define CC 96
#define HH 512
#define WW 96
#define HWX (HH*WW)     // 49152
#define OC  (3*CC)      // 288
#define SS  100         // smem row stride (floats); rows 400B -> 16B aligned
#define NT  384         // 12 warps

typedef unsigned long long u64;

__device__ __align__(16) float g_WT[CC*OC];   // W'^T: [c][o], BN folded
__device__ float g_bias[OC];

struct __align__(16) U64x2 { u64 lo, hi; };

// ---------------- packed f32x2 helpers ----------------
__device__ __forceinline__ u64 ffma2(u64 a, u64 b, u64 c){
    u64 d; asm("fma.rn.f32x2 %0, %1, %2, %3;" : "=l"(d) : "l"(a), "l"(b), "l"(c)); return d;
}
__device__ __forceinline__ u64 add2(u64 a, u64 b){
    u64 d; asm("add.rn.f32x2 %0, %1, %2;" : "=l"(d) : "l"(a), "l"(b)); return d;
}
__device__ __forceinline__ u64 pack2(float x){
    u64 d; asm("mov.b64 %0, {%1, %1};" : "=l"(d) : "f"(x)); return d;
}

// ---------------- prep: fold BN into QKV weights ----------------
__global__ void prep_kernel(const float* __restrict__ qkv_w, const float* __restrict__ qkv_b,
                            const float* __restrict__ gam, const float* __restrict__ bet,
                            const float* __restrict__ mn,  const float* __restrict__ vr){
    int o = blockIdx.x;
    int c = threadIdx.x;
    __shared__ float red[CC];
    float inv   = gam[c] * rsqrtf(vr[c] + 1e-5f);
    float shift = bet[c] - mn[c]*inv;
    float wv = qkv_w[o*CC + c];
    g_WT[c*OC + o] = wv * inv;
    red[c] = wv * shift;
    __syncthreads();
    if (c < 32){
        float s = red[c] + red[c+32] + red[c+64];
        #pragma unroll
        for (int off = 16; off; off >>= 1) s += __shfl_down_sync(0xffffffffu, s, off);
        if (c == 0) g_bias[o] = s + qkv_b[o];
    }
}

// ---------------- shared GEMM inner loop ----------------
// Thread tile: rows aB[c*SS + i] (i<3, per-lane), col-pairs bB[c*SS + 2j] (j<4, per-warp).
// aB pre-offset by 3*lane (conflict-free LDS.32, stride 3 coprime 32).
// bB pre-offset by 8*warp -> WARP-UNIFORM address: 2x LDS.128 broadcast.
__device__ __forceinline__ void gemm96(const float* __restrict__ aB,
                                       const float* __restrict__ bB,
                                       u64 acc[3][4]){
    #pragma unroll 4
    for (int c = 0; c < CC; ++c){
        const float* ar = aB + c*SS;
        const float* br = bB + c*SS;
        U64x2 b0 = *(const U64x2*)(br);       // broadcast LDS.128
        U64x2 b1 = *(const U64x2*)(br + 4);
        u64 bv[4] = { b0.lo, b0.hi, b1.lo, b1.hi };
        u64 A[3]  = { pack2(ar[0]), pack2(ar[1]), pack2(ar[2]) };
        #pragma unroll
        for (int i = 0; i < 3; ++i)
            #pragma unroll
            for (int j = 0; j < 4; ++j)
                acc[i][j] = ffma2(A[i], bv[j], acc[i][j]);
    }
}

__device__ __forceinline__ void store_tile(float* dst, u64 acc[3][4]){
    // dst pre-offset by (3*lane)*SS + 8*warp
    #pragma unroll
    for (int i = 0; i < 3; ++i)
        #pragma unroll
        for (int j = 0; j < 4; ++j)
            *(u64*)(dst + i*SS + 2*j) = acc[i][j];
}

// ---------------- fused attention kernel ----------------
// one CTA per (b,h). 384 threads = 12 warps.
// warp owns 8 cols (bOff = 8*warp), lane owns 3 rows (aOff = 3*lane).
__global__ __launch_bounds__(NT) void attn_kernel(const float* __restrict__ x,
                                                  float* __restrict__ out){
    extern __shared__ float sm[];
    float* xs = sm;              // x tile [c][w] (pristine, for residual)
    float* ws = sm + 1*CC*SS;    // weights block -> score [q][k] -> final out [c][w]
    float* qs = sm + 2*CC*SS;    // q [o][w]; later attn^T [k][q]
    float* ks = sm + 3*CC*SS;    // k [o][w]
    float* vt = sm + 4*CC*SS;    // v transposed [w][o]

    const int t    = threadIdx.x;
    const int lane = t & 31;
    const int warp = t >> 5;     // 0..11
    const int aOff = 3*lane;     // row offset (per-lane)
    const int bOff = 8*warp;     // col offset (per-warp, uniform)
    const int bh = blockIdx.x;
    const int b  = bh >> 9;      // H = 512
    const int h  = bh & 511;
    const size_t base = (size_t)b*CC*HWX + (size_t)h*WW;

    // ---- load x tile (coalesced float4) ----
    for (int idx = t; idx < CC*24; idx += NT){
        int c = idx/24, j = idx%24;
        *(float4*)&xs[c*SS + 4*j] = *(const float4*)(x + base + (size_t)c*HWX + 4*j);
    }

    u64 acc[3][4];

    // ---- QKV: 3 passes. p=0: q[o][w], p=1: k[o][w], p=2: v^T[w][o] ----
    for (int p = 0; p < 3; ++p){
        if (p) __syncthreads();                 // done reading ws from prior pass
        for (int idx = t; idx < CC*24; idx += NT){
            int c = idx/24, j = idx%24;
            *(float4*)&ws[c*SS + 4*j] = *(const float4*)&g_WT[c*OC + p*CC + 4*j];
        }
        __syncthreads();

        if (p < 2){
            // rows = o (weights), cols = w (x)
            #pragma unroll
            for (int i = 0; i < 3; ++i){
                u64 b2 = pack2(g_bias[p*CC + aOff + i]);
                #pragma unroll
                for (int j = 0; j < 4; ++j) acc[i][j] = b2;
            }
            gemm96(ws + aOff, xs + bOff, acc);
            store_tile(((p == 0) ? qs : ks) + aOff*SS + bOff, acc);
        } else {
            // v with swapped roles: rows = w (x), cols = o (weights) -> v^T
            #pragma unroll
            for (int j = 0; j < 4; ++j){
                u64 bj = *(const u64*)&g_bias[2*CC + bOff + 2*j];
                #pragma unroll
                for (int i = 0; i < 3; ++i) acc[i][j] = bj;
            }
            gemm96(xs + aOff, ws + bOff, acc);
            store_tile(vt + aOff*SS + bOff, acc);
        }
    }
    __syncthreads();

    // ---- score[q][k] = sum_c q[c][q] * k[c][k] -> ws ----
    #pragma unroll
    for (int i = 0; i < 3; ++i)
        #pragma unroll
        for (int j = 0; j < 4; ++j) acc[i][j] = 0ull;
    gemm96(qs + aOff, ks + bOff, acc);
    store_tile(ws + aOff*SS + bOff, acc);
    __syncthreads();

    // ---- softmax over k; write TRANSPOSED attn^T[k][q] into qs ----
    {
        for (int r = warp*8; r < warp*8 + 8; ++r){
            const float* row = &ws[r*SS];
            float v0 = row[lane], v1 = row[lane+32], v2 = row[lane+64];
            float m = fmaxf(v0, fmaxf(v1, v2));
            #pragma unroll
            for (int o2 = 16; o2; o2 >>= 1) m = fmaxf(m, __shfl_xor_sync(0xffffffffu, m, o2));
            float e0 = __expf(v0 - m), e1 = __expf(v1 - m), e2 = __expf(v2 - m);
            float s = e0 + e1 + e2;
            #pragma unroll
            for (int o2 = 16; o2; o2 >>= 1) s += __shfl_xor_sync(0xffffffffu, s, o2);
            float inv = 1.0f / s;
            qs[(lane   )*SS + r] = e0*inv;
            qs[(lane+32)*SS + r] = e1*inv;
            qs[(lane+64)*SS + r] = e2*inv;
        }
    }
    __syncthreads();

    // ---- AV: out[c][q] = sum_k v^T[k][c] * attn^T[k][q] ----
    #pragma unroll
    for (int i = 0; i < 3; ++i)
        #pragma unroll
        for (int j = 0; j < 4; ++j) acc[i][j] = 0ull;
    gemm96(vt + aOff, qs + bOff, acc);

    // residual add into ws ([c][w] layout), then coalesced writeout
    #pragma unroll
    for (int i = 0; i < 3; ++i){
        int c = aOff + i;
        const float* xr = &xs[c*SS + bOff];
        float* wr = &ws[c*SS + bOff];
        #pragma unroll
        for (int j = 0; j < 4; ++j){
            u64 r = *(const u64*)(xr + 2*j);
            *(u64*)(wr + 2*j) = add2(acc[i][j], r);
        }
    }
    __syncthreads();

    for (int idx = t; idx < CC*24; idx += NT){
        int c = idx/24, j = idx%24;
        *(float4*)(out + base + (size_t)c*HWX + 4*j) = *(const float4*)&ws[c*SS + 4*j];
    }
}

extern "C" void kernel_launch(void* const* d_in, const int* in_sizes, int n_in,
                              void* d_out, int out_size){
    const float* x     = (const float*)d_in[0];
    const float* gam   = (const float*)d_in[1];
    const float* bet   = (const float*)d_in[2];
    const float* mn    = (const float*)d_in[3];
    const float* vr    = (const float*)d_in[4];
    const float* qkv_w = (const float*)d_in[5];
    const float* qkv_b = (const float*)d_in[6];
    float* out = (float*)d_out;

    cudaFuncSetAttribute(attn_kernel, cudaFuncAttributeMaxDynamicSharedMemorySize, CC*SS*5*sizeof(float));

    prep_kernel<<<OC, CC>>>(qkv_w, qkv_b, gam, bet, mn, vr);
    attn_kernel<<<BB*HH, NT, CC*SS*5*sizeof(float)>>>(x, out);
}

// round 9
// speedup vs baseline: 2.1419x; 1.7410x over previous
#include <cuda_runtime.h>
#include <cuda_bf16.h>
#include <cstdint>

#define BB 8
#define CC 96
#define HH 512
#define WW 96
#define HWX (HH*WW)     // 49152
#define OC  288
#define NT  384         // 12 warps

typedef unsigned int u32;
typedef unsigned short u16;

// prep outputs: BN-folded W' split planes, [o][c] packed as u32 (even c low)
__device__ u32   g_WAh[OC*48];
__device__ u32   g_WAl[OC*48];
__device__ float g_bias[OC];

// ---- smem map (bytes). bf16 planes: 96 rows x 104 b16 (stride 208B) ----
#define PL   208
#define PLSZ (96*PL)        // 19968
#define O_XBH 0             // x split hi  [c][w]   (B for QKV)
#define O_XBL (PLSZ)        // x split lo
#define O_SC  0             // -> score f32 [qw][kw] stride 100 (reuse)
#define O_WAH (2*PLSZ)      // W pass plane hi [o][c] (A for QKV)
#define O_WAL (3*PLSZ)
#define O_ATH (2*PLSZ)      // -> attn hi [qw][kw]   (A for AV, reuse)
#define O_ATL (3*PLSZ)
#define O_QTH (4*PLSZ)      // qT hi [w][c]          (A for score)
#define O_QTL (5*PLSZ)
#define O_OF  (4*PLSZ)      // -> out f32 [c][w] stride 100 (reuse)
#define O_KH  (6*PLSZ)      // k hi [c][w]           (B for score)
#define O_KL  (7*PLSZ)
#define O_VH  (8*PLSZ)      // vT hi [w][c]          (B for AV)
#define O_VL  (9*PLSZ)
#define SMEM_BYTES (10*PLSZ)   // 199680

__device__ __forceinline__ u32 smem_u32(const void* p){
    u32 a; asm("{ .reg .u64 t; cvta.to.shared.u64 t, %1; cvt.u32.u64 %0, t; }" : "=r"(a) : "l"(p));
    return a;
}
#define LDSM4(r0,r1,r2,r3,addr) \
    asm volatile("ldmatrix.sync.aligned.m8n8.x4.shared.b16 {%0,%1,%2,%3}, [%4];" \
        : "=r"(r0),"=r"(r1),"=r"(r2),"=r"(r3) : "r"(addr))
#define LDSM2T(r0,r1,addr) \
    asm volatile("ldmatrix.sync.aligned.m8n8.x2.trans.shared.b16 {%0,%1}, [%2];" \
        : "=r"(r0),"=r"(r1) : "r"(addr))
#define MMA_BF16(d,a0,a1,a2,a3,b0,b1) \
    asm volatile("mma.sync.aligned.m16n8k16.row.col.f32.bf16.bf16.f32 " \
        "{%0,%1,%2,%3},{%4,%5,%6,%7},{%8,%9},{%0,%1,%2,%3};" \
        : "+f"((d)[0]),"+f"((d)[1]),"+f"((d)[2]),"+f"((d)[3]) \
        : "r"(a0),"r"(a1),"r"(a2),"r"(a3),"r"(b0),"r"(b1))

__device__ __forceinline__ void split2(float f, u16& h, u16& l){
    __nv_bfloat16 bh = __float2bfloat16_rn(f);
    float r = f - __bfloat162float(bh);
    __nv_bfloat16 bl = __float2bfloat16_rn(r);
    h = __bfloat16_as_ushort(bh); l = __bfloat16_as_ushort(bl);
}

// ---------------- prep: fold BN into W, 3-way outputs ----------------
__global__ void prep_kernel(const float* __restrict__ qkv_w, const float* __restrict__ qkv_b,
                            const float* __restrict__ gam, const float* __restrict__ bet,
                            const float* __restrict__ mn,  const float* __restrict__ vr){
    int o = blockIdx.x;    // 0..287
    int c = threadIdx.x;   // 0..95
    __shared__ float wrow[CC];
    __shared__ float red[CC];
    float inv   = gam[c] * rsqrtf(vr[c] + 1e-5f);
    float shift = bet[c] - mn[c]*inv;
    float wv = qkv_w[o*CC + c];
    wrow[c] = wv * inv;
    red[c]  = wv * shift;
    __syncthreads();
    if (c < 32){
        float s = red[c] + red[c+32] + red[c+64];
        #pragma unroll
        for (int off = 16; off; off >>= 1) s += __shfl_down_sync(0xffffffffu, s, off);
        if (c == 0) g_bias[o] = s + qkv_b[o];
    }
    if (c < 48){
        u16 h0,l0,h1,l1;
        split2(wrow[2*c],   h0, l0);
        split2(wrow[2*c+1], h1, l1);
        g_WAh[o*48 + c] = (u32)h0 | ((u32)h1 << 16);
        g_WAl[o*48 + c] = (u32)l0 | ((u32)l1 << 16);
    }
}

// ---- one 96x96x96 GEMM stage on tensor cores (3-product bf16 split) ----
// warp (mt, nh) owns rows [16mt,16mt+16) x cols [48nh, 48nh+48).
// aOff/bOff: lane-specific byte offsets (mt/nh folded in).
__device__ __forceinline__ void mma96(u32 Ah, u32 Al, u32 Bh, u32 Bl,
                                      float (&acc)[6][4], u32 aOff, u32 bOff){
    #pragma unroll
    for (int kt = 0; kt < 6; ++kt){
        u32 ah0,ah1,ah2,ah3, al0,al1,al2,al3;
        LDSM4(ah0,ah1,ah2,ah3, Ah + aOff + kt*32);
        LDSM4(al0,al1,al2,al3, Al + aOff + kt*32);
        #pragma unroll
        for (int n6 = 0; n6 < 6; ++n6){
            u32 bo = bOff + (u32)(kt*(16*PL) + n6*16);
            u32 bh0,bh1, bl0,bl1;
            LDSM2T(bh0,bh1, Bh + bo);
            LDSM2T(bl0,bl1, Bl + bo);
            MMA_BF16(acc[n6], ah0,ah1,ah2,ah3, bh0,bh1);
            MMA_BF16(acc[n6], ah0,ah1,ah2,ah3, bl0,bl1);
            MMA_BF16(acc[n6], al0,al1,al2,al3, bh0,bh1);
        }
    }
}

// ---------------- fused attention kernel ----------------
__global__ __launch_bounds__(NT) void attn_kernel(const float* __restrict__ x,
                                                  float* __restrict__ out){
    extern __shared__ char smc[];
    const int t    = threadIdx.x;
    const int lane = t & 31;
    const int warp = t >> 5;     // 0..11
    const int mt = warp >> 1;    // m16 tile 0..5
    const int nh = warp & 1;     // n half (6 n8-tiles each)
    const int g  = lane >> 2;    // 0..7
    const int tq = lane & 3;     // 0..3
    const int bh = blockIdx.x;
    const int b  = bh >> 9;
    const int h  = bh & 511;
    const size_t base = (size_t)b*CC*HWX + (size_t)h*WW;

    // ldmatrix lane address offsets
    const int ai = lane >> 3, ar = lane & 7;
    const u32 aOff = (u32)((mt*16 + (ai&1)*8 + ar)*PL + ((ai>>1)*8)*2);
    const int bT = lane & 15;
    const u32 bOff = (u32)(((bT>>3)*8 + (bT&7))*PL + nh*96);

    const u32 sb = smem_u32(smc);

    // ---- load x, 3-way split into XB planes [c][w] ----
    for (int idx = t; idx < CC*24; idx += NT){
        int c = idx/24, j = idx%24;
        float4 v = *(const float4*)(x + base + (size_t)c*HWX + 4*j);
        u16 hh[4], ll[4];
        split2(v.x, hh[0], ll[0]); split2(v.y, hh[1], ll[1]);
        split2(v.z, hh[2], ll[2]); split2(v.w, hh[3], ll[3]);
        u32 off = (u32)(c*PL + 8*j);
        *(u32*)(smc + O_XBH + off)     = (u32)hh[0] | ((u32)hh[1] << 16);
        *(u32*)(smc + O_XBH + off + 4) = (u32)hh[2] | ((u32)hh[3] << 16);
        *(u32*)(smc + O_XBL + off)     = (u32)ll[0] | ((u32)ll[1] << 16);
        *(u32*)(smc + O_XBL + off + 4) = (u32)ll[2] | ((u32)ll[3] << 16);
    }

    float acc[6][4];

    // ---- QKV: 3 passes (q, k, v), M=o(96) N=w(96) K=c(96) ----
    for (int p = 0; p < 3; ++p){
        __syncthreads();   // prior pass done reading WA (and x-split visible for p=0)
        for (int idx = t; idx < CC*48; idx += NT){
            int o = idx/48, j = idx%48;
            *(u32*)(smc + O_WAH + o*PL + 4*j) = g_WAh[(p*CC + o)*48 + j];
            *(u32*)(smc + O_WAL + o*PL + 4*j) = g_WAl[(p*CC + o)*48 + j];
        }
        __syncthreads();

        float bg  = g_bias[p*CC + mt*16 + g];
        float bg8 = g_bias[p*CC + mt*16 + g + 8];
        #pragma unroll
        for (int n6 = 0; n6 < 6; ++n6){
            acc[n6][0] = bg; acc[n6][1] = bg;
            acc[n6][2] = bg8; acc[n6][3] = bg8;
        }
        mma96(sb + O_WAH, sb + O_WAL, sb + O_XBH, sb + O_XBL, acc, aOff, bOff);

        // epilogue: split to bf16 planes in the layout the next stage needs
        #pragma unroll
        for (int n6 = 0; n6 < 6; ++n6){
            int w0 = nh*48 + n6*8 + 2*tq;
            int o0 = mt*16 + g;
            u16 h0,l0;
            if (p == 1){
                // k: natural [c][w], packed u32 stores
                u16 h1,l1;
                split2(acc[n6][0], h0, l0); split2(acc[n6][1], h1, l1);
                *(u32*)(smc + O_KH + o0*PL + w0*2) = (u32)h0 | ((u32)h1 << 16);
                *(u32*)(smc + O_KL + o0*PL + w0*2) = (u32)l0 | ((u32)l1 << 16);
                split2(acc[n6][2], h0, l0); split2(acc[n6][3], h1, l1);
                *(u32*)(smc + O_KH + (o0+8)*PL + w0*2) = (u32)h0 | ((u32)h1 << 16);
                *(u32*)(smc + O_KL + (o0+8)*PL + w0*2) = (u32)l0 | ((u32)l1 << 16);
            } else {
                // q or v: transposed [w][c]
                int OH = (p == 0) ? O_QTH : O_VH;
                int OL = (p == 0) ? O_QTL : O_VL;
                split2(acc[n6][0], h0, l0);
                *(u16*)(smc + OH + (w0  )*PL + o0*2) = h0;
                *(u16*)(smc + OL + (w0  )*PL + o0*2) = l0;
                split2(acc[n6][1], h0, l0);
                *(u16*)(smc + OH + (w0+1)*PL + o0*2) = h0;
                *(u16*)(smc + OL + (w0+1)*PL + o0*2) = l0;
                split2(acc[n6][2], h0, l0);
                *(u16*)(smc + OH + (w0  )*PL + (o0+8)*2) = h0;
                *(u16*)(smc + OL + (w0  )*PL + (o0+8)*2) = l0;
                split2(acc[n6][3], h0, l0);
                *(u16*)(smc + OH + (w0+1)*PL + (o0+8)*2) = h0;
                *(u16*)(smc + OL + (w0+1)*PL + (o0+8)*2) = l0;
            }
        }
    }
    __syncthreads();

    // ---- score: M=qw N=kw K=c; A=qT, B=k -> f32 [qw][kw] stride 100 ----
    #pragma unroll
    for (int n6 = 0; n6 < 6; ++n6){
        acc[n6][0]=0.f; acc[n6][1]=0.f; acc[n6][2]=0.f; acc[n6][3]=0.f;
    }
    mma96(sb + O_QTH, sb + O_QTL, sb + O_KH, sb + O_KL, acc, aOff, bOff);
    {
        float* sc = (float*)(smc + O_SC);
        #pragma unroll
        for (int n6 = 0; n6 < 6; ++n6){
            int kw0 = nh*48 + n6*8 + 2*tq;
            int qw0 = mt*16 + g;
            sc[(qw0  )*100 + kw0    ] = acc[n6][0];
            sc[(qw0  )*100 + kw0 + 1] = acc[n6][1];
            sc[(qw0+8)*100 + kw0    ] = acc[n6][2];
            sc[(qw0+8)*100 + kw0 + 1] = acc[n6][3];
        }
    }
    __syncthreads();

    // ---- softmax over kw; write attn split planes [qw][kw] ----
    {
        const float* sc = (const float*)(smc + O_SC);
        for (int r = warp*8; r < warp*8 + 8; ++r){
            const float* row = sc + r*100;
            float v0 = row[lane], v1 = row[lane+32], v2 = row[lane+64];
            float m = fmaxf(v0, fmaxf(v1, v2));
            #pragma unroll
            for (int o2 = 16; o2; o2 >>= 1) m = fmaxf(m, __shfl_xor_sync(0xffffffffu, m, o2));
            float e0 = __expf(v0 - m), e1 = __expf(v1 - m), e2 = __expf(v2 - m);
            float s = e0 + e1 + e2;
            #pragma unroll
            for (int o2 = 16; o2; o2 >>= 1) s += __shfl_xor_sync(0xffffffffu, s, o2);
            float inv = 1.0f / s;
            u16 hh, ll;
            split2(e0*inv, hh, ll);
            *(u16*)(smc + O_ATH + r*PL + (lane   )*2) = hh;
            *(u16*)(smc + O_ATL + r*PL + (lane   )*2) = ll;
            split2(e1*inv, hh, ll);
            *(u16*)(smc + O_ATH + r*PL + (lane+32)*2) = hh;
            *(u16*)(smc + O_ATL + r*PL + (lane+32)*2) = ll;
            split2(e2*inv, hh, ll);
            *(u16*)(smc + O_ATH + r*PL + (lane+64)*2) = hh;
            *(u16*)(smc + O_ATL + r*PL + (lane+64)*2) = ll;
        }
    }
    __syncthreads();

    // ---- AV: M=qw N=c K=kw; A=attn, B=vT -> f32 out staging [c][w] ----
    #pragma unroll
    for (int n6 = 0; n6 < 6; ++n6){
        acc[n6][0]=0.f; acc[n6][1]=0.f; acc[n6][2]=0.f; acc[n6][3]=0.f;
    }
    mma96(sb + O_ATH, sb + O_ATL, sb + O_VH, sb + O_VL, acc, aOff, bOff);
    {
        float* of = (float*)(smc + O_OF);
        #pragma unroll
        for (int n6 = 0; n6 < 6; ++n6){
            int c0  = nh*48 + n6*8 + 2*tq;
            int qw0 = mt*16 + g;
            of[(c0  )*100 + qw0    ] = acc[n6][0];
            of[(c0+1)*100 + qw0    ] = acc[n6][1];
            of[(c0  )*100 + qw0 + 8] = acc[n6][2];
            of[(c0+1)*100 + qw0 + 8] = acc[n6][3];
        }
    }
    __syncthreads();

    // ---- residual (re-read x) + coalesced writeout ----
    {
        const float* of = (const float*)(smc + O_OF);
        for (int idx = t; idx < CC*24; idx += NT){
            int c = idx/24, j = idx%24;
            float4 xv = *(const float4*)(x + base + (size_t)c*HWX + 4*j);
            float4 ov = *(const float4*)(of + c*100 + 4*j);
            ov.x += xv.x; ov.y += xv.y; ov.z += xv.z; ov.w += xv.w;
            *(float4*)(out + base + (size_t)c*HWX + 4*j) = ov;
        }
    }
}

extern "C" void kernel_launch(void* const* d_in, const int* in_sizes, int n_in,
                              void* d_out, int out_size){
    const float* x     = (const float*)d_in[0];
    const float* gam   = (const float*)d_in[1];
    const float* bet   = (const float*)d_in[2];
    const float* mn    = (const float*)d_in[3];
    const float* vr    = (const float*)d_in[4];
    const float* qkv_w = (const float*)d_in[5];
    const float* qkv_b = (const float*)d_in[6];
    float* out = (float*)d_out;

    cudaFuncSetAttribute(attn_kernel, cudaFuncAttributeMaxDynamicSharedMemorySize, SMEM_BYTES);

    prep_kernel<<<OC, CC>>>(qkv_w, qkv_b, gam, bet, mn, vr);
    attn_kernel<<<BB*HH, NT, SMEM_BYTES>>>(x, out);
}

// round 10
// speedup vs baseline: 2.4123x; 1.1262x over previous
#include <cuda_runtime.h>
#include <cuda_bf16.h>
#include <cstdint>

#define BB 8
#define CC 96
#define HH 512
#define WW 96
#define HWX (HH*WW)     // 49152
#define OC  288
#define NT  384         // 12 warps

typedef unsigned int u32;
typedef unsigned short u16;

// prep outputs: W' (BN folded) in EXACT mma A-fragment order, hi/lo bf16 planes
// index: ((p*36 + mt*6 + kt)*32 + lane)*4 + q   (q = a0..a3)
__device__ u32   g_WfragH[108*32*4];
__device__ u32   g_WfragL[108*32*4];
__device__ float g_bias[OC];

// ---- smem map (bytes). bf16 planes: 96 rows x 104 b16 (stride 208B) ----
#define PL   208
#define PLSZ (96*PL)        // 19968
#define O_XBH 0             // x split hi  [c][w]  (B for QKV) -> out f32 staging
#define O_XBL (PLSZ)
#define O_OF  0             // out f32 [c][w] stride 100 (reuse XB)
#define O_QTH (2*PLSZ)      // qT hi [w][c]  (A for score) -> score f32
#define O_QTL (3*PLSZ)
#define O_SC  (2*PLSZ)      // score f32 [qw][kw] stride 100 (reuse qT)
#define O_KH  (4*PLSZ)      // k hi [c][w]   (B for score) -> attn planes
#define O_KL  (5*PLSZ)
#define O_ATH (4*PLSZ)      // attn hi [qw][kw] (A for AV, reuse K)
#define O_ATL (5*PLSZ)
#define O_VTH (6*PLSZ)      // vT hi [w][c]  (B for AV)
#define O_VTL (7*PLSZ)
#define SMEM_BYTES (8*PLSZ)    // 159744

__device__ __forceinline__ u32 smem_u32(const void* p){
    u32 a; asm("{ .reg .u64 t; cvta.to.shared.u64 t, %1; cvt.u32.u64 %0, t; }" : "=r"(a) : "l"(p));
    return a;
}
#define LDSM4(r0,r1,r2,r3,addr) \
    asm volatile("ldmatrix.sync.aligned.m8n8.x4.shared.b16 {%0,%1,%2,%3}, [%4];" \
        : "=r"(r0),"=r"(r1),"=r"(r2),"=r"(r3) : "r"(addr))
#define LDSM4T(r0,r1,r2,r3,addr) \
    asm volatile("ldmatrix.sync.aligned.m8n8.x4.trans.shared.b16 {%0,%1,%2,%3}, [%4];" \
        : "=r"(r0),"=r"(r1),"=r"(r2),"=r"(r3) : "r"(addr))
#define MMA_BF16(d,a0,a1,a2,a3,b0,b1) \
    asm volatile("mma.sync.aligned.m16n8k16.row.col.f32.bf16.bf16.f32 " \
        "{%0,%1,%2,%3},{%4,%5,%6,%7},{%8,%9},{%0,%1,%2,%3};" \
        : "+f"((d)[0]),"+f"((d)[1]),"+f"((d)[2]),"+f"((d)[3]) \
        : "r"(a0),"r"(a1),"r"(a2),"r"(a3),"r"(b0),"r"(b1))

__device__ __forceinline__ void split2(float f, u16& h, u16& l){
    __nv_bfloat16 bh = __float2bfloat16_rn(f);
    float r = f - __bfloat162float(bh);
    __nv_bfloat16 bl = __float2bfloat16_rn(r);
    h = __bfloat16_as_ushort(bh); l = __bfloat16_as_ushort(bl);
}

// one k16 step: 18 MMAs, B loaded as 3 hi + 3 lo x4-trans pairs
__device__ __forceinline__ void kt_body(float (&acc)[6][4],
        u32 ah0,u32 ah1,u32 ah2,u32 ah3,
        u32 al0,u32 al1,u32 al2,u32 al3,
        u32 Bh, u32 Bl, u32 bo){
    #pragma unroll
    for (int p2 = 0; p2 < 3; ++p2){
        u32 h0,h1,h2,h3, l0,l1,l2,l3;
        LDSM4T(h0,h1,h2,h3, Bh + bo + p2*32);
        LDSM4T(l0,l1,l2,l3, Bl + bo + p2*32);
        MMA_BF16(acc[2*p2  ], ah0,ah1,ah2,ah3, h0,h1);
        MMA_BF16(acc[2*p2+1], ah0,ah1,ah2,ah3, h2,h3);
        MMA_BF16(acc[2*p2  ], ah0,ah1,ah2,ah3, l0,l1);
        MMA_BF16(acc[2*p2+1], ah0,ah1,ah2,ah3, l2,l3);
        MMA_BF16(acc[2*p2  ], al0,al1,al2,al3, h0,h1);
        MMA_BF16(acc[2*p2+1], al0,al1,al2,al3, h2,h3);
    }
}

// ---------------- prep: bias ----------------
__global__ void prep_bias(const float* __restrict__ qkv_w, const float* __restrict__ qkv_b,
                          const float* __restrict__ gam, const float* __restrict__ bet,
                          const float* __restrict__ mn,  const float* __restrict__ vr){
    int o = blockIdx.x;
    int c = threadIdx.x;
    __shared__ float red[CC];
    float inv   = gam[c] * rsqrtf(vr[c] + 1e-5f);
    float shift = bet[c] - mn[c]*inv;
    red[c] = qkv_w[o*CC + c] * shift;
    __syncthreads();
    if (c < 32){
        float s = red[c] + red[c+32] + red[c+64];
        #pragma unroll
        for (int off = 16; off; off >>= 1) s += __shfl_down_sync(0xffffffffu, s, off);
        if (c == 0) g_bias[o] = s + qkv_b[o];
    }
}

// ---------------- prep: W' in A-fragment order ----------------
__global__ void prep_frag(const float* __restrict__ qkv_w,
                          const float* __restrict__ gam, const float* __restrict__ vr){
    int blk = blockIdx.x;          // 108 = p*36 + mt*6 + kt
    int p  = blk / 36;
    int mt = (blk / 6) % 6;
    int kt = blk % 6;
    int lane = threadIdx.x;        // 32
    int r  = lane >> 2;
    int c0 = 2*(lane & 3);
    int base = (blk*32 + lane)*4;
    #pragma unroll
    for (int q = 0; q < 4; ++q){
        int ro = mt*16 + r + (q & 1)*8;
        int co = kt*16 + c0 + (q >> 1)*8;
        float inv0 = gam[co]   * rsqrtf(vr[co]   + 1e-5f);
        float inv1 = gam[co+1] * rsqrtf(vr[co+1] + 1e-5f);
        u16 h0,l0,h1,l1;
        split2(qkv_w[(p*CC + ro)*CC + co]   * inv0, h0, l0);
        split2(qkv_w[(p*CC + ro)*CC + co+1] * inv1, h1, l1);
        g_WfragH[base + q] = (u32)h0 | ((u32)h1 << 16);
        g_WfragL[base + q] = (u32)l0 | ((u32)l1 << 16);
    }
}

// ---------------- fused attention kernel ----------------
__global__ __launch_bounds__(NT) void attn_kernel(const float* __restrict__ x,
                                                  float* __restrict__ out){
    extern __shared__ char smc[];
    const int t    = threadIdx.x;
    const int lane = t & 31;
    const int warp = t >> 5;     // 0..11
    const int mt = warp >> 1;    // m16 tile 0..5
    const int nh = warp & 1;     // n half
    const int g  = lane >> 2;    // 0..7
    const int tq = lane & 3;     // 0..3
    const int bh = blockIdx.x;
    const int b  = bh >> 9;
    const int h  = bh & 511;
    const size_t base = (size_t)b*CC*HWX + (size_t)h*WW;

    // A-side (smem, x4) lane offset
    const int ai = lane >> 3, ar = lane & 7;
    const u32 aOff = (u32)((mt*16 + (ai&1)*8 + ar)*PL + ((ai>>1)*8)*2);
    // B-side (x4 trans) lane offset
    const u32 bOff4 = (u32)(((lane & 7) + ((lane >> 3) & 1)*8)*PL + nh*96 + (lane >> 4)*16);

    const u32 sb = smem_u32(smc);

    // ---- load x, split into XB planes [c][w] ----
    for (int idx = t; idx < CC*24; idx += NT){
        int c = idx/24, j = idx%24;
        float4 v = *(const float4*)(x + base + (size_t)c*HWX + 4*j);
        u16 hh[4], ll[4];
        split2(v.x, hh[0], ll[0]); split2(v.y, hh[1], ll[1]);
        split2(v.z, hh[2], ll[2]); split2(v.w, hh[3], ll[3]);
        u32 off = (u32)(c*PL + 8*j);
        *(u32*)(smc + O_XBH + off)     = (u32)hh[0] | ((u32)hh[1] << 16);
        *(u32*)(smc + O_XBH + off + 4) = (u32)hh[2] | ((u32)hh[3] << 16);
        *(u32*)(smc + O_XBL + off)     = (u32)ll[0] | ((u32)ll[1] << 16);
        *(u32*)(smc + O_XBL + off + 4) = (u32)ll[2] | ((u32)ll[3] << 16);
    }
    __syncthreads();   // (1) XB visible

    float acc[6][4];

    // ---- QKV: 3 passes back-to-back, A from global fragments ----
    #pragma unroll 1
    for (int p = 0; p < 3; ++p){
        const u32* WfH = g_WfragH + (p*36 + mt*6)*128;
        const u32* WfL = g_WfragL + (p*36 + mt*6)*128;

        float bg  = g_bias[p*CC + mt*16 + g];
        float bg8 = g_bias[p*CC + mt*16 + g + 8];
        #pragma unroll
        for (int n6 = 0; n6 < 6; ++n6){
            acc[n6][0] = bg;  acc[n6][1] = bg;
            acc[n6][2] = bg8; acc[n6][3] = bg8;
        }
        #pragma unroll
        for (int kt = 0; kt < 6; ++kt){
            uint4 AH = *(const uint4*)(WfH + kt*128 + lane*4);
            uint4 AL = *(const uint4*)(WfL + kt*128 + lane*4);
            kt_body(acc, AH.x,AH.y,AH.z,AH.w, AL.x,AL.y,AL.z,AL.w,
                    sb + O_XBH, sb + O_XBL, bOff4 + (u32)(kt*16*PL));
        }

        // epilogue -> split planes (disjoint per pass, no barrier needed)
        #pragma unroll
        for (int n6 = 0; n6 < 6; ++n6){
            int w0 = nh*48 + n6*8 + 2*tq;
            int o0 = mt*16 + g;
            u16 h0,l0;
            if (p == 1){
                u16 h1,l1;
                split2(acc[n6][0], h0, l0); split2(acc[n6][1], h1, l1);
                *(u32*)(smc + O_KH + o0*PL + w0*2) = (u32)h0 | ((u32)h1 << 16);
                *(u32*)(smc + O_KL + o0*PL + w0*2) = (u32)l0 | ((u32)l1 << 16);
                split2(acc[n6][2], h0, l0); split2(acc[n6][3], h1, l1);
                *(u32*)(smc + O_KH + (o0+8)*PL + w0*2) = (u32)h0 | ((u32)h1 << 16);
                *(u32*)(smc + O_KL + (o0+8)*PL + w0*2) = (u32)l0 | ((u32)l1 << 16);
            } else {
                int OH = (p == 0) ? O_QTH : O_VTH;
                int OL = (p == 0) ? O_QTL : O_VTL;
                split2(acc[n6][0], h0, l0);
                *(u16*)(smc + OH + (w0  )*PL + o0*2) = h0;
                *(u16*)(smc + OL + (w0  )*PL + o0*2) = l0;
                split2(acc[n6][1], h0, l0);
                *(u16*)(smc + OH + (w0+1)*PL + o0*2) = h0;
                *(u16*)(smc + OL + (w0+1)*PL + o0*2) = l0;
                split2(acc[n6][2], h0, l0);
                *(u16*)(smc + OH + (w0  )*PL + (o0+8)*2) = h0;
                *(u16*)(smc + OL + (w0  )*PL + (o0+8)*2) = l0;
                split2(acc[n6][3], h0, l0);
                *(u16*)(smc + OH + (w0+1)*PL + (o0+8)*2) = h0;
                *(u16*)(smc + OL + (w0+1)*PL + (o0+8)*2) = l0;
            }
        }
    }
    __syncthreads();   // (2) qT, k, vT visible

    // ---- score: A=qT (smem), B=k ----
    #pragma unroll
    for (int n6 = 0; n6 < 6; ++n6){
        acc[n6][0]=0.f; acc[n6][1]=0.f; acc[n6][2]=0.f; acc[n6][3]=0.f;
    }
    #pragma unroll
    for (int kt = 0; kt < 6; ++kt){
        u32 ah0,ah1,ah2,ah3, al0,al1,al2,al3;
        LDSM4(ah0,ah1,ah2,ah3, sb + O_QTH + aOff + kt*32);
        LDSM4(al0,al1,al2,al3, sb + O_QTL + aOff + kt*32);
        kt_body(acc, ah0,ah1,ah2,ah3, al0,al1,al2,al3,
                sb + O_KH, sb + O_KL, bOff4 + (u32)(kt*16*PL));
    }
    __syncthreads();   // (3) all warps done reading qT/K
    {
        float* sc = (float*)(smc + O_SC);
        #pragma unroll
        for (int n6 = 0; n6 < 6; ++n6){
            int kw0 = nh*48 + n6*8 + 2*tq;
            int qw0 = mt*16 + g;
            sc[(qw0  )*100 + kw0    ] = acc[n6][0];
            sc[(qw0  )*100 + kw0 + 1] = acc[n6][1];
            sc[(qw0+8)*100 + kw0    ] = acc[n6][2];
            sc[(qw0+8)*100 + kw0 + 1] = acc[n6][3];
        }
    }
    __syncthreads();   // (4) score visible

    // ---- softmax over kw; attn planes into K area ----
    {
        const float* sc = (const float*)(smc + O_SC);
        for (int r = warp*8; r < warp*8 + 8; ++r){
            const float* row = sc + r*100;
            float v0 = row[lane], v1 = row[lane+32], v2 = row[lane+64];
            float m = fmaxf(v0, fmaxf(v1, v2));
            #pragma unroll
            for (int o2 = 16; o2; o2 >>= 1) m = fmaxf(m, __shfl_xor_sync(0xffffffffu, m, o2));
            float e0 = __expf(v0 - m), e1 = __expf(v1 - m), e2 = __expf(v2 - m);
            float s = e0 + e1 + e2;
            #pragma unroll
            for (int o2 = 16; o2; o2 >>= 1) s += __shfl_xor_sync(0xffffffffu, s, o2);
            float inv = 1.0f / s;
            u16 hh, ll;
            split2(e0*inv, hh, ll);
            *(u16*)(smc + O_ATH + r*PL + (lane   )*2) = hh;
            *(u16*)(smc + O_ATL + r*PL + (lane   )*2) = ll;
            split2(e1*inv, hh, ll);
            *(u16*)(smc + O_ATH + r*PL + (lane+32)*2) = hh;
            *(u16*)(smc + O_ATL + r*PL + (lane+32)*2) = ll;
            split2(e2*inv, hh, ll);
            *(u16*)(smc + O_ATH + r*PL + (lane+64)*2) = hh;
            *(u16*)(smc + O_ATL + r*PL + (lane+64)*2) = ll;
        }
    }
    __syncthreads();   // (5) attn visible

    // ---- AV: A=attn, B=vT -> out f32 [c][w] into XB area ----
    #pragma unroll
    for (int n6 = 0; n6 < 6; ++n6){
        acc[n6][0]=0.f; acc[n6][1]=0.f; acc[n6][2]=0.f; acc[n6][3]=0.f;
    }
    #pragma unroll
    for (int kt = 0; kt < 6; ++kt){
        u32 ah0,ah1,ah2,ah3, al0,al1,al2,al3;
        LDSM4(ah0,ah1,ah2,ah3, sb + O_ATH + aOff + kt*32);
        LDSM4(al0,al1,al2,al3, sb + O_ATL + aOff + kt*32);
        kt_body(acc, ah0,ah1,ah2,ah3, al0,al1,al2,al3,
                sb + O_VTH, sb + O_VTL, bOff4 + (u32)(kt*16*PL));
    }
    {
        float* of = (float*)(smc + O_OF);   // XB area (dead)
        #pragma unroll
        for (int n6 = 0; n6 < 6; ++n6){
            int c0  = nh*48 + n6*8 + 2*tq;
            int qw0 = mt*16 + g;
            of[(c0  )*100 + qw0    ] = acc[n6][0];
            of[(c0+1)*100 + qw0    ] = acc[n6][1];
            of[(c0  )*100 + qw0 + 8] = acc[n6][2];
            of[(c0+1)*100 + qw0 + 8] = acc[n6][3];
        }
    }
    __syncthreads();   // (6) out staging visible

    // ---- residual (re-read x) + coalesced writeout ----
    {
        const float* of = (const float*)(smc + O_OF);
        for (int idx = t; idx < CC*24; idx += NT){
            int c = idx/24, j = idx%24;
            float4 xv = *(const float4*)(x + base + (size_t)c*HWX + 4*j);
            float4 ov = *(const float4*)(of + c*100 + 4*j);
            ov.x += xv.x; ov.y += xv.y; ov.z += xv.z; ov.w += xv.w;
            *(float4*)(out + base + (size_t)c*HWX + 4*j) = ov;
        }
    }
}

extern "C" void kernel_launch(void* const* d_in, const int* in_sizes, int n_in,
                              void* d_out, int out_size){
    const float* x     = (const float*)d_in[0];
    const float* gam   = (const float*)d_in[1];
    const float* bet   = (const float*)d_in[2];
    const float* mn    = (const float*)d_in[3];
    const float* vr    = (const float*)d_in[4];
    const float* qkv_w = (const float*)d_in[5];
    const float* qkv_b = (const float*)d_in[6];
    float* out = (float*)d_out;

    cudaFuncSetAttribute(attn_kernel, cudaFuncAttributeMaxDynamicSharedMemorySize, SMEM_BYTES);

    prep_bias<<<OC, CC>>>(qkv_w, qkv_b, gam, bet, mn, vr);
    prep_frag<<<108, 32>>>(qkv_w, gam, vr);
    attn_kernel<<<BB*HH, NT, SMEM_BYTES>>>(x, out);
}

// round 11
// speedup vs baseline: 2.8489x; 1.1810x over previous
#include <cuda_runtime.h>
#include <cuda_bf16.h>
#include <cstdint>

#define BB 8
#define CC 96
#define HH 512
#define WW 96
#define HWX (HH*WW)     // 49152
#define OC  288
#define NT  768         // 24 warps

typedef unsigned int u32;
typedef unsigned short u16;

// prep outputs: W' (BN folded) in EXACT mma A-fragment order, hi/lo bf16 planes
// index: ((p*36 + mt*6 + kt)*32 + lane)*4 + q
__device__ u32   g_WfragH[108*32*4];
__device__ u32   g_WfragL[108*32*4];
__device__ float g_bias[OC];

// ---- smem map (bytes). bf16 planes: 96 rows x 104 b16 (stride 208B) ----
#define PL   208
#define PLSZ (96*PL)        // 19968
#define O_XBH 0             // x split hi  [c][w]  (B for QKV) -> out f32 staging
#define O_XBL (PLSZ)
#define O_OF  0             // out f32 [c][w] stride 100 (reuse XB)
#define O_QTH (2*PLSZ)      // qT hi [w][c]  (A for score) -> score f32
#define O_QTL (3*PLSZ)
#define O_SC  (2*PLSZ)      // score f32 [qw][kw] stride 100 (reuse qT)
#define O_KH  (4*PLSZ)      // k hi [c][w]   (B for score) -> attn planes
#define O_KL  (5*PLSZ)
#define O_ATH (4*PLSZ)      // attn hi [qw][kw] (A for AV, reuse K)
#define O_ATL (5*PLSZ)
#define O_VTH (6*PLSZ)      // vT hi [w][c]  (B for AV)
#define O_VTL (7*PLSZ)
#define SMEM_BYTES (8*PLSZ)    // 159744

__device__ __forceinline__ u32 smem_u32(const void* p){
    u32 a; asm("{ .reg .u64 t; cvta.to.shared.u64 t, %1; cvt.u32.u64 %0, t; }" : "=r"(a) : "l"(p));
    return a;
}
#define LDSM4(r0,r1,r2,r3,addr) \
    asm volatile("ldmatrix.sync.aligned.m8n8.x4.shared.b16 {%0,%1,%2,%3}, [%4];" \
        : "=r"(r0),"=r"(r1),"=r"(r2),"=r"(r3) : "r"(addr))
#define LDSM4T(r0,r1,r2,r3,addr) \
    asm volatile("ldmatrix.sync.aligned.m8n8.x4.trans.shared.b16 {%0,%1,%2,%3}, [%4];" \
        : "=r"(r0),"=r"(r1),"=r"(r2),"=r"(r3) : "r"(addr))
#define LDSM2T(r0,r1,addr) \
    asm volatile("ldmatrix.sync.aligned.m8n8.x2.trans.shared.b16 {%0,%1}, [%2];" \
        : "=r"(r0),"=r"(r1) : "r"(addr))
#define MMA_BF16(d,a0,a1,a2,a3,b0,b1) \
    asm volatile("mma.sync.aligned.m16n8k16.row.col.f32.bf16.bf16.f32 " \
        "{%0,%1,%2,%3},{%4,%5,%6,%7},{%8,%9},{%0,%1,%2,%3};" \
        : "+f"((d)[0]),"+f"((d)[1]),"+f"((d)[2]),"+f"((d)[3]) \
        : "r"(a0),"r"(a1),"r"(a2),"r"(a3),"r"(b0),"r"(b1))

__device__ __forceinline__ void split2(float f, u16& h, u16& l){
    __nv_bfloat16 bh = __float2bfloat16_rn(f);
    float r = f - __bfloat162float(bh);
    __nv_bfloat16 bl = __float2bfloat16_rn(r);
    h = __bfloat16_as_ushort(bh); l = __bfloat16_as_ushort(bl);
}

// one k16 step for a 24-col quarter: 9 MMAs (hh, hl, lh)
__device__ __forceinline__ void kt_body(float (&acc)[3][4],
        u32 ah0,u32 ah1,u32 ah2,u32 ah3,
        u32 al0,u32 al1,u32 al2,u32 al3,
        u32 Bh, u32 Bl, u32 bo4, u32 bo2){
    u32 h0,h1,h2,h3, g0,g1;
    u32 l0,l1,l2,l3, m0,m1;
    LDSM4T(h0,h1,h2,h3, Bh + bo4);
    LDSM2T(g0,g1,       Bh + bo2);
    LDSM4T(l0,l1,l2,l3, Bl + bo4);
    LDSM2T(m0,m1,       Bl + bo2);
    MMA_BF16(acc[0], ah0,ah1,ah2,ah3, h0,h1);
    MMA_BF16(acc[1], ah0,ah1,ah2,ah3, h2,h3);
    MMA_BF16(acc[2], ah0,ah1,ah2,ah3, g0,g1);
    MMA_BF16(acc[0], ah0,ah1,ah2,ah3, l0,l1);
    MMA_BF16(acc[1], ah0,ah1,ah2,ah3, l2,l3);
    MMA_BF16(acc[2], ah0,ah1,ah2,ah3, m0,m1);
    MMA_BF16(acc[0], al0,al1,al2,al3, h0,h1);
    MMA_BF16(acc[1], al0,al1,al2,al3, h2,h3);
    MMA_BF16(acc[2], al0,al1,al2,al3, g0,g1);
}

// ---------------- prep: bias ----------------
__global__ void prep_bias(const float* __restrict__ qkv_w, const float* __restrict__ qkv_b,
                          const float* __restrict__ gam, const float* __restrict__ bet,
                          const float* __restrict__ mn,  const float* __restrict__ vr){
    int o = blockIdx.x;
    int c = threadIdx.x;
    __shared__ float red[CC];
    float inv   = gam[c] * rsqrtf(vr[c] + 1e-5f);
    float shift = bet[c] - mn[c]*inv;
    red[c] = qkv_w[o*CC + c] * shift;
    __syncthreads();
    if (c < 32){
        float s = red[c] + red[c+32] + red[c+64];
        #pragma unroll
        for (int off = 16; off; off >>= 1) s += __shfl_down_sync(0xffffffffu, s, off);
        if (c == 0) g_bias[o] = s + qkv_b[o];
    }
}

// ---------------- prep: W' in A-fragment order ----------------
__global__ void prep_frag(const float* __restrict__ qkv_w,
                          const float* __restrict__ gam, const float* __restrict__ vr){
    int blk = blockIdx.x;          // 108 = p*36 + mt*6 + kt
    int p  = blk / 36;
    int mt = (blk / 6) % 6;
    int kt = blk % 6;
    int lane = threadIdx.x;        // 32
    int r  = lane >> 2;
    int c0 = 2*(lane & 3);
    int base = (blk*32 + lane)*4;
    #pragma unroll
    for (int q = 0; q < 4; ++q){
        int ro = mt*16 + r + (q & 1)*8;
        int co = kt*16 + c0 + (q >> 1)*8;
        float inv0 = gam[co]   * rsqrtf(vr[co]   + 1e-5f);
        float inv1 = gam[co+1] * rsqrtf(vr[co+1] + 1e-5f);
        u16 h0,l0,h1,l1;
        split2(qkv_w[(p*CC + ro)*CC + co]   * inv0, h0, l0);
        split2(qkv_w[(p*CC + ro)*CC + co+1] * inv1, h1, l1);
        g_WfragH[base + q] = (u32)h0 | ((u32)h1 << 16);
        g_WfragL[base + q] = (u32)l0 | ((u32)l1 << 16);
    }
}

// ---------------- fused attention kernel ----------------
// 768 threads = 24 warps. warp = (mt, nq): mt = warp>>2 (m16 tile), nq = warp&3 (24-col quarter).
__global__ __launch_bounds__(NT) void attn_kernel(const float* __restrict__ x,
                                                  float* __restrict__ out){
    extern __shared__ char smc[];
    const int t    = threadIdx.x;
    const int lane = t & 31;
    const int warp = t >> 5;     // 0..23
    const int mt = warp >> 2;    // 0..5
    const int nq = warp & 3;     // 0..3
    const int g  = lane >> 2;    // 0..7
    const int tq = lane & 3;     // 0..3
    const int bh = blockIdx.x;
    const int b  = bh >> 9;
    const int h  = bh & 511;
    const size_t base = (size_t)b*CC*HWX + (size_t)h*WW;

    // A-side (smem, x4) lane offset
    const int ai = lane >> 3, ar = lane & 7;
    const u32 aOff = (u32)((mt*16 + (ai&1)*8 + ar)*PL + ((ai>>1)*8)*2);
    // B-side lane offsets: x4-trans (16 cols) and x2-trans (last 8 cols)
    const u32 bRow  = (u32)(((lane & 7) + ((lane >> 3) & 1)*8)*PL);
    const u32 bOff4 = bRow + (u32)(nq*48 + ((lane >> 4)&1)*16);
    const u32 bOff2 = (u32)((((lane & 15) & 7) + (((lane & 15) >> 3))*8)*PL) + (u32)(nq*48 + 32);

    const u32 sb = smem_u32(smc);

    // ---- load x, split into XB planes [c][w] ----
    for (int idx = t; idx < CC*24; idx += NT){
        int c = idx/24, j = idx%24;
        float4 v = *(const float4*)(x + base + (size_t)c*HWX + 4*j);
        u16 hh[4], ll[4];
        split2(v.x, hh[0], ll[0]); split2(v.y, hh[1], ll[1]);
        split2(v.z, hh[2], ll[2]); split2(v.w, hh[3], ll[3]);
        u32 off = (u32)(c*PL + 8*j);
        *(u32*)(smc + O_XBH + off)     = (u32)hh[0] | ((u32)hh[1] << 16);
        *(u32*)(smc + O_XBH + off + 4) = (u32)hh[2] | ((u32)hh[3] << 16);
        *(u32*)(smc + O_XBL + off)     = (u32)ll[0] | ((u32)ll[1] << 16);
        *(u32*)(smc + O_XBL + off + 4) = (u32)ll[2] | ((u32)ll[3] << 16);
    }
    __syncthreads();   // (1) XB visible

    float acc[3][4];

    // ---- QKV: 3 passes back-to-back, A from global fragments ----
    #pragma unroll 1
    for (int p = 0; p < 3; ++p){
        const u32* WfH = g_WfragH + (p*36 + mt*6)*128;
        const u32* WfL = g_WfragL + (p*36 + mt*6)*128;

        float bg  = g_bias[p*CC + mt*16 + g];
        float bg8 = g_bias[p*CC + mt*16 + g + 8];
        #pragma unroll
        for (int n6 = 0; n6 < 3; ++n6){
            acc[n6][0] = bg;  acc[n6][1] = bg;
            acc[n6][2] = bg8; acc[n6][3] = bg8;
        }
        #pragma unroll
        for (int kt = 0; kt < 6; ++kt){
            uint4 AH = *(const uint4*)(WfH + kt*128 + lane*4);
            uint4 AL = *(const uint4*)(WfL + kt*128 + lane*4);
            kt_body(acc, AH.x,AH.y,AH.z,AH.w, AL.x,AL.y,AL.z,AL.w,
                    sb + O_XBH, sb + O_XBL,
                    bOff4 + (u32)(kt*16*PL), bOff2 + (u32)(kt*16*PL));
        }

        // epilogue -> split planes (disjoint per pass, no barrier needed)
        #pragma unroll
        for (int n6 = 0; n6 < 3; ++n6){
            int w0 = nq*24 + n6*8 + 2*tq;
            int o0 = mt*16 + g;
            u16 h0,l0;
            if (p == 1){
                u16 h1,l1;
                split2(acc[n6][0], h0, l0); split2(acc[n6][1], h1, l1);
                *(u32*)(smc + O_KH + o0*PL + w0*2) = (u32)h0 | ((u32)h1 << 16);
                *(u32*)(smc + O_KL + o0*PL + w0*2) = (u32)l0 | ((u32)l1 << 16);
                split2(acc[n6][2], h0, l0); split2(acc[n6][3], h1, l1);
                *(u32*)(smc + O_KH + (o0+8)*PL + w0*2) = (u32)h0 | ((u32)h1 << 16);
                *(u32*)(smc + O_KL + (o0+8)*PL + w0*2) = (u32)l0 | ((u32)l1 << 16);
            } else {
                int OH = (p == 0) ? O_QTH : O_VTH;
                int OL = (p == 0) ? O_QTL : O_VTL;
                split2(acc[n6][0], h0, l0);
                *(u16*)(smc + OH + (w0  )*PL + o0*2) = h0;
                *(u16*)(smc + OL + (w0  )*PL + o0*2) = l0;
                split2(acc[n6][1], h0, l0);
                *(u16*)(smc + OH + (w0+1)*PL + o0*2) = h0;
                *(u16*)(smc + OL + (w0+1)*PL + o0*2) = l0;
                split2(acc[n6][2], h0, l0);
                *(u16*)(smc + OH + (w0  )*PL + (o0+8)*2) = h0;
                *(u16*)(smc + OL + (w0  )*PL + (o0+8)*2) = l0;
                split2(acc[n6][3], h0, l0);
                *(u16*)(smc + OH + (w0+1)*PL + (o0+8)*2) = h0;
                *(u16*)(smc + OL + (w0+1)*PL + (o0+8)*2) = l0;
            }
        }
    }
    __syncthreads();   // (2) qT, k, vT visible

    // ---- score: A=qT (smem), B=k ----
    #pragma unroll
    for (int n6 = 0; n6 < 3; ++n6){
        acc[n6][0]=0.f; acc[n6][1]=0.f; acc[n6][2]=0.f; acc[n6][3]=0.f;
    }
    #pragma unroll
    for (int kt = 0; kt < 6; ++kt){
        u32 ah0,ah1,ah2,ah3, al0,al1,al2,al3;
        LDSM4(ah0,ah1,ah2,ah3, sb + O_QTH + aOff + kt*32);
        LDSM4(al0,al1,al2,al3, sb + O_QTL + aOff + kt*32);
        kt_body(acc, ah0,ah1,ah2,ah3, al0,al1,al2,al3,
                sb + O_KH, sb + O_KL,
                bOff4 + (u32)(kt*16*PL), bOff2 + (u32)(kt*16*PL));
    }
    __syncthreads();   // (3) all warps done reading qT/K
    {
        float* sc = (float*)(smc + O_SC);
        #pragma unroll
        for (int n6 = 0; n6 < 3; ++n6){
            int kw0 = nq*24 + n6*8 + 2*tq;
            int qw0 = mt*16 + g;
            sc[(qw0  )*100 + kw0    ] = acc[n6][0];
            sc[(qw0  )*100 + kw0 + 1] = acc[n6][1];
            sc[(qw0+8)*100 + kw0    ] = acc[n6][2];
            sc[(qw0+8)*100 + kw0 + 1] = acc[n6][3];
        }
    }
    __syncthreads();   // (4) score visible

    // ---- softmax over kw; attn planes into K area (4 rows per warp) ----
    {
        const float* sc = (const float*)(smc + O_SC);
        for (int r = warp*4; r < warp*4 + 4; ++r){
            const float* row = sc + r*100;
            float v0 = row[lane], v1 = row[lane+32], v2 = row[lane+64];
            float m = fmaxf(v0, fmaxf(v1, v2));
            #pragma unroll
            for (int o2 = 16; o2; o2 >>= 1) m = fmaxf(m, __shfl_xor_sync(0xffffffffu, m, o2));
            float e0 = __expf(v0 - m), e1 = __expf(v1 - m), e2 = __expf(v2 - m);
            float s = e0 + e1 + e2;
            #pragma unroll
            for (int o2 = 16; o2; o2 >>= 1) s += __shfl_xor_sync(0xffffffffu, s, o2);
            float inv = 1.0f / s;
            u16 hh, ll;
            split2(e0*inv, hh, ll);
            *(u16*)(smc + O_ATH + r*PL + (lane   )*2) = hh;
            *(u16*)(smc + O_ATL + r*PL + (lane   )*2) = ll;
            split2(e1*inv, hh, ll);
            *(u16*)(smc + O_ATH + r*PL + (lane+32)*2) = hh;
            *(u16*)(smc + O_ATL + r*PL + (lane+32)*2) = ll;
            split2(e2*inv, hh, ll);
            *(u16*)(smc + O_ATH + r*PL + (lane+64)*2) = hh;
            *(u16*)(smc + O_ATL + r*PL + (lane+64)*2) = ll;
        }
    }
    __syncthreads();   // (5) attn visible

    // ---- AV: A=attn, B=vT -> out f32 [c][w] into XB area ----
    #pragma unroll
    for (int n6 = 0; n6 < 3; ++n6){
        acc[n6][0]=0.f; acc[n6][1]=0.f; acc[n6][2]=0.f; acc[n6][3]=0.f;
    }
    #pragma unroll
    for (int kt = 0; kt < 6; ++kt){
        u32 ah0,ah1,ah2,ah3, al0,al1,al2,al3;
        LDSM4(ah0,ah1,ah2,ah3, sb + O_ATH + aOff + kt*32);
        LDSM4(al0,al1,al2,al3, sb + O_ATL + aOff + kt*32);
        kt_body(acc, ah0,ah1,ah2,ah3, al0,al1,al2,al3,
                sb + O_VTH, sb + O_VTL,
                bOff4 + (u32)(kt*16*PL), bOff2 + (u32)(kt*16*PL));
    }
    {
        float* of = (float*)(smc + O_OF);   // XB area (dead)
        #pragma unroll
        for (int n6 = 0; n6 < 3; ++n6){
            int c0  = nq*24 + n6*8 + 2*tq;
            int qw0 = mt*16 + g;
            of[(c0  )*100 + qw0    ] = acc[n6][0];
            of[(c0+1)*100 + qw0    ] = acc[n6][1];
            of[(c0  )*100 + qw0 + 8] = acc[n6][2];
            of[(c0+1)*100 + qw0 + 8] = acc[n6][3];
        }
    }
    __syncthreads();   // (6) out staging visible

    // ---- residual (re-read x) + coalesced writeout ----
    {
        const float* of = (const float*)(smc + O_OF);
        for (int idx = t; idx < CC*24; idx += NT){
            int c = idx/24, j = idx%24;
            float4 xv = *(const float4*)(x + base + (size_t)c*HWX + 4*j);
            float4 ov = *(const float4*)(of + c*100 + 4*j);
            ov.x += xv.x; ov.y += xv.y; ov.z += xv.z; ov.w += xv.w;
            *(float4*)(out + base + (size_t)c*HWX + 4*j) = ov;
        }
    }
}

extern "C" void kernel_launch(void* const* d_in, const int* in_sizes, int n_in,
                              void* d_out, int out_size){
    const float* x     = (const float*)d_in[0];
    const float* gam   = (const float*)d_in[1];
    const float* bet   = (const float*)d_in[2];
    const float* mn    = (const float*)d_in[3];
    const float* vr    = (const float*)d_in[4];
    const float* qkv_w = (const float*)d_in[5];
    const float* qkv_b = (const float*)d_in[6];
    float* out = (float*)d_out;

    cudaFuncSetAttribute(attn_kernel, cudaFuncAttributeMaxDynamicSharedMemorySize, SMEM_BYTES);

    prep_bias<<<OC, CC>>>(qkv_w, qkv_b, gam, bet, mn, vr);
    prep_frag<<<108, 32>>>(qkv_w, gam, vr);
    attn_kernel<<<BB*HH, NT, SMEM_BYTES>>>(x, out);
}

// round 12
// speedup vs baseline: 3.0899x; 1.0846x over previous
#include <cuda_runtime.h>
#include <cuda_bf16.h>
#include <cstdint>

#define BB 8
#define CC 96
#define HH 512
#define WW 96
#define HWX (HH*WW)     // 49152
#define OC  288
#define NT  768         // 24 warps

typedef unsigned int u32;
typedef unsigned short u16;

// prep outputs: W' (BN folded) in EXACT mma A-fragment order, hi/lo bf16 planes
// index: ((p*36 + mt*6 + kt)*32 + lane)*4 + q
__device__ u32   g_WfragH[108*32*4];
__device__ u32   g_WfragL[108*32*4];
__device__ float g_bias[OC];

// ---- smem map (bytes). bf16 planes: 96 rows x 104 b16 (stride 208B) ----
#define PL   208
#define PLSZ (96*PL)        // 19968
#define O_XBH 0             // x split hi [c][w] (B for QKV) -> score f32 -> out f32 staging
#define O_XBL (PLSZ)
#define O_SC  0             // score f32 [qw][kw] stride 100 (XB area, dead after QKV)
#define O_OF  0             // out f32 [c][w] stride 100 (XB area, dead after softmax)
#define O_QTH (2*PLSZ)      // qT hi [w][c]  (A for score)
#define O_QTL (3*PLSZ)
#define O_KH  (4*PLSZ)      // k hi [c][w]   (B for score) -> attn planes
#define O_KL  (5*PLSZ)
#define O_ATH (4*PLSZ)      // attn hi [qw][kw] (A for AV, reuse K)
#define O_ATL (5*PLSZ)
#define O_VTH (6*PLSZ)      // vT hi [w][c]  (B for AV)
#define O_VTL (7*PLSZ)
#define SMEM_BYTES (8*PLSZ)    // 159744

__device__ __forceinline__ u32 smem_u32(const void* p){
    u32 a; asm("{ .reg .u64 t; cvta.to.shared.u64 t, %1; cvt.u32.u64 %0, t; }" : "=r"(a) : "l"(p));
    return a;
}
#define LDSM4(r0,r1,r2,r3,addr) \
    asm volatile("ldmatrix.sync.aligned.m8n8.x4.shared.b16 {%0,%1,%2,%3}, [%4];" \
        : "=r"(r0),"=r"(r1),"=r"(r2),"=r"(r3) : "r"(addr))
#define LDSM4T(r0,r1,r2,r3,addr) \
    asm volatile("ldmatrix.sync.aligned.m8n8.x4.trans.shared.b16 {%0,%1,%2,%3}, [%4];" \
        : "=r"(r0),"=r"(r1),"=r"(r2),"=r"(r3) : "r"(addr))
#define LDSM2T(r0,r1,addr) \
    asm volatile("ldmatrix.sync.aligned.m8n8.x2.trans.shared.b16 {%0,%1}, [%2];" \
        : "=r"(r0),"=r"(r1) : "r"(addr))
#define MMA_BF16(d,a0,a1,a2,a3,b0,b1) \
    asm volatile("mma.sync.aligned.m16n8k16.row.col.f32.bf16.bf16.f32 " \
        "{%0,%1,%2,%3},{%4,%5,%6,%7},{%8,%9},{%0,%1,%2,%3};" \
        : "+f"((d)[0]),"+f"((d)[1]),"+f"((d)[2]),"+f"((d)[3]) \
        : "r"(a0),"r"(a1),"r"(a2),"r"(a3),"r"(b0),"r"(b1))

__device__ __forceinline__ void split2(float f, u16& h, u16& l){
    __nv_bfloat16 bh = __float2bfloat16_rn(f);
    float r = f - __bfloat162float(bh);
    __nv_bfloat16 bl = __float2bfloat16_rn(r);
    h = __bfloat16_as_ushort(bh); l = __bfloat16_as_ushort(bl);
}

// one k16 step for a 24-col quarter: 9 MMAs (hh, hl, lh), B frags passed in
__device__ __forceinline__ void kt_mma(float (&acc)[3][4],
        u32 ah0,u32 ah1,u32 ah2,u32 ah3,
        u32 al0,u32 al1,u32 al2,u32 al3,
        u32 h0,u32 h1,u32 h2,u32 h3,u32 g0,u32 g1,
        u32 l0,u32 l1,u32 l2,u32 l3,u32 m0,u32 m1){
    MMA_BF16(acc[0], ah0,ah1,ah2,ah3, h0,h1);
    MMA_BF16(acc[1], ah0,ah1,ah2,ah3, h2,h3);
    MMA_BF16(acc[2], ah0,ah1,ah2,ah3, g0,g1);
    MMA_BF16(acc[0], ah0,ah1,ah2,ah3, l0,l1);
    MMA_BF16(acc[1], ah0,ah1,ah2,ah3, l2,l3);
    MMA_BF16(acc[2], ah0,ah1,ah2,ah3, m0,m1);
    MMA_BF16(acc[0], al0,al1,al2,al3, h0,h1);
    MMA_BF16(acc[1], al0,al1,al2,al3, h2,h3);
    MMA_BF16(acc[2], al0,al1,al2,al3, g0,g1);
}

// ---------------- prep: bias ----------------
__global__ void prep_bias(const float* __restrict__ qkv_w, const float* __restrict__ qkv_b,
                          const float* __restrict__ gam, const float* __restrict__ bet,
                          const float* __restrict__ mn,  const float* __restrict__ vr){
    int o = blockIdx.x;
    int c = threadIdx.x;
    __shared__ float red[CC];
    float inv   = gam[c] * rsqrtf(vr[c] + 1e-5f);
    float shift = bet[c] - mn[c]*inv;
    red[c] = qkv_w[o*CC + c] * shift;
    __syncthreads();
    if (c < 32){
        float s = red[c] + red[c+32] + red[c+64];
        #pragma unroll
        for (int off = 16; off; off >>= 1) s += __shfl_down_sync(0xffffffffu, s, off);
        if (c == 0) g_bias[o] = s + qkv_b[o];
    }
}

// ---------------- prep: W' in A-fragment order ----------------
__global__ void prep_frag(const float* __restrict__ qkv_w,
                          const float* __restrict__ gam, const float* __restrict__ vr){
    int blk = blockIdx.x;          // 108 = p*36 + mt*6 + kt
    int p  = blk / 36;
    int mt = (blk / 6) % 6;
    int kt = blk % 6;
    int lane = threadIdx.x;        // 32
    int r  = lane >> 2;
    int c0 = 2*(lane & 3);
    int base = (blk*32 + lane)*4;
    #pragma unroll
    for (int q = 0; q < 4; ++q){
        int ro = mt*16 + r + (q & 1)*8;
        int co = kt*16 + c0 + (q >> 1)*8;
        float inv0 = gam[co]   * rsqrtf(vr[co]   + 1e-5f);
        float inv1 = gam[co+1] * rsqrtf(vr[co+1] + 1e-5f);
        u16 h0,l0,h1,l1;
        split2(qkv_w[(p*CC + ro)*CC + co]   * inv0, h0, l0);
        split2(qkv_w[(p*CC + ro)*CC + co+1] * inv1, h1, l1);
        g_WfragH[base + q] = (u32)h0 | ((u32)h1 << 16);
        g_WfragL[base + q] = (u32)l0 | ((u32)l1 << 16);
    }
}

// ---------------- fused attention kernel ----------------
// 768 threads = 24 warps. warp = (mt, nq): mt = warp>>2, nq = warp&3 (24-col quarter).
__global__ __launch_bounds__(NT) void attn_kernel(const float* __restrict__ x,
                                                  float* __restrict__ out){
    extern __shared__ char smc[];
    const int t    = threadIdx.x;
    const int lane = t & 31;
    const int warp = t >> 5;     // 0..23
    const int mt = warp >> 2;    // 0..5
    const int nq = warp & 3;     // 0..3
    const int g  = lane >> 2;    // 0..7
    const int tq = lane & 3;     // 0..3
    const int bh = blockIdx.x;
    const int b  = bh >> 9;
    const int h  = bh & 511;
    const size_t base = (size_t)b*CC*HWX + (size_t)h*WW;

    // A-side (smem, x4) lane offset
    const int ai = lane >> 3, ar = lane & 7;
    const u32 aOff = (u32)((mt*16 + (ai&1)*8 + ar)*PL + ((ai>>1)*8)*2);
    // B-side lane offsets: x4-trans (16 cols) and x2-trans (last 8 cols)
    const u32 bRow  = (u32)(((lane & 7) + ((lane >> 3) & 1)*8)*PL);
    const u32 bOff4 = bRow + (u32)(nq*48 + ((lane >> 4)&1)*16);
    const u32 bOff2 = (u32)((((lane & 15) & 7) + (((lane & 15) >> 3))*8)*PL) + (u32)(nq*48 + 32);

    const u32 sb = smem_u32(smc);

    // ---- load x, split into XB planes [c][w] ----
    for (int idx = t; idx < CC*24; idx += NT){
        int c = idx/24, j = idx%24;
        float4 v = *(const float4*)(x + base + (size_t)c*HWX + 4*j);
        u16 hh[4], ll[4];
        split2(v.x, hh[0], ll[0]); split2(v.y, hh[1], ll[1]);
        split2(v.z, hh[2], ll[2]); split2(v.w, hh[3], ll[3]);
        u32 off = (u32)(c*PL + 8*j);
        *(u32*)(smc + O_XBH + off)     = (u32)hh[0] | ((u32)hh[1] << 16);
        *(u32*)(smc + O_XBH + off + 4) = (u32)hh[2] | ((u32)hh[3] << 16);
        *(u32*)(smc + O_XBL + off)     = (u32)ll[0] | ((u32)ll[1] << 16);
        *(u32*)(smc + O_XBL + off + 4) = (u32)ll[2] | ((u32)ll[3] << 16);
    }
    __syncthreads();   // (1) XB visible

    // ---- QKV: kt-outer, pass-inner; B fragments loaded ONCE per kt ----
    {
        float acc3[3][3][4];
        #pragma unroll
        for (int p = 0; p < 3; ++p){
            float bg  = g_bias[p*CC + mt*16 + g];
            float bg8 = g_bias[p*CC + mt*16 + g + 8];
            #pragma unroll
            for (int n6 = 0; n6 < 3; ++n6){
                acc3[p][n6][0] = bg;  acc3[p][n6][1] = bg;
                acc3[p][n6][2] = bg8; acc3[p][n6][3] = bg8;
            }
        }
        const u32* WfH = g_WfragH + (mt*6)*128 + lane*4;
        const u32* WfL = g_WfragL + (mt*6)*128 + lane*4;

        #pragma unroll
        for (int kt = 0; kt < 6; ++kt){
            u32 h0,h1,h2,h3, g0,g1, l0,l1,l2,l3, m0,m1;
            LDSM4T(h0,h1,h2,h3, sb + O_XBH + bOff4 + (u32)(kt*16*PL));
            LDSM2T(g0,g1,       sb + O_XBH + bOff2 + (u32)(kt*16*PL));
            LDSM4T(l0,l1,l2,l3, sb + O_XBL + bOff4 + (u32)(kt*16*PL));
            LDSM2T(m0,m1,       sb + O_XBL + bOff2 + (u32)(kt*16*PL));
            #pragma unroll
            for (int p = 0; p < 3; ++p){
                uint4 AH = *(const uint4*)(WfH + (p*36 + kt)*128);
                uint4 AL = *(const uint4*)(WfL + (p*36 + kt)*128);
                kt_mma(acc3[p], AH.x,AH.y,AH.z,AH.w, AL.x,AL.y,AL.z,AL.w,
                       h0,h1,h2,h3,g0,g1, l0,l1,l2,l3,m0,m1);
            }
        }

        // epilogues -> split planes (disjoint areas, no intra-QKV barrier)
        #pragma unroll
        for (int p = 0; p < 3; ++p){
            #pragma unroll
            for (int n6 = 0; n6 < 3; ++n6){
                int w0 = nq*24 + n6*8 + 2*tq;
                int o0 = mt*16 + g;
                u16 h0,l0;
                if (p == 1){
                    u16 h1,l1;
                    split2(acc3[p][n6][0], h0, l0); split2(acc3[p][n6][1], h1, l1);
                    *(u32*)(smc + O_KH + o0*PL + w0*2) = (u32)h0 | ((u32)h1 << 16);
                    *(u32*)(smc + O_KL + o0*PL + w0*2) = (u32)l0 | ((u32)l1 << 16);
                    split2(acc3[p][n6][2], h0, l0); split2(acc3[p][n6][3], h1, l1);
                    *(u32*)(smc + O_KH + (o0+8)*PL + w0*2) = (u32)h0 | ((u32)h1 << 16);
                    *(u32*)(smc + O_KL + (o0+8)*PL + w0*2) = (u32)l0 | ((u32)l1 << 16);
                } else {
                    int OH = (p == 0) ? O_QTH : O_VTH;
                    int OL = (p == 0) ? O_QTL : O_VTL;
                    split2(acc3[p][n6][0], h0, l0);
                    *(u16*)(smc + OH + (w0  )*PL + o0*2) = h0;
                    *(u16*)(smc + OL + (w0  )*PL + o0*2) = l0;
                    split2(acc3[p][n6][1], h0, l0);
                    *(u16*)(smc + OH + (w0+1)*PL + o0*2) = h0;
                    *(u16*)(smc + OL + (w0+1)*PL + o0*2) = l0;
                    split2(acc3[p][n6][2], h0, l0);
                    *(u16*)(smc + OH + (w0  )*PL + (o0+8)*2) = h0;
                    *(u16*)(smc + OL + (w0  )*PL + (o0+8)*2) = l0;
                    split2(acc3[p][n6][3], h0, l0);
                    *(u16*)(smc + OH + (w0+1)*PL + (o0+8)*2) = h0;
                    *(u16*)(smc + OL + (w0+1)*PL + (o0+8)*2) = l0;
                }
            }
        }
    }
    __syncthreads();   // (2) qT, k, vT visible; XB reads done

    float acc[3][4];

    // ---- score: A=qT (smem), B=k -> f32 into XB area (dead) ----
    #pragma unroll
    for (int n6 = 0; n6 < 3; ++n6){
        acc[n6][0]=0.f; acc[n6][1]=0.f; acc[n6][2]=0.f; acc[n6][3]=0.f;
    }
    #pragma unroll
    for (int kt = 0; kt < 6; ++kt){
        u32 ah0,ah1,ah2,ah3, al0,al1,al2,al3;
        u32 h0,h1,h2,h3, g0,g1, l0,l1,l2,l3, m0,m1;
        LDSM4(ah0,ah1,ah2,ah3, sb + O_QTH + aOff + kt*32);
        LDSM4(al0,al1,al2,al3, sb + O_QTL + aOff + kt*32);
        LDSM4T(h0,h1,h2,h3, sb + O_KH + bOff4 + (u32)(kt*16*PL));
        LDSM2T(g0,g1,       sb + O_KH + bOff2 + (u32)(kt*16*PL));
        LDSM4T(l0,l1,l2,l3, sb + O_KL + bOff4 + (u32)(kt*16*PL));
        LDSM2T(m0,m1,       sb + O_KL + bOff2 + (u32)(kt*16*PL));
        kt_mma(acc, ah0,ah1,ah2,ah3, al0,al1,al2,al3,
               h0,h1,h2,h3,g0,g1, l0,l1,l2,l3,m0,m1);
    }
    {
        float* sc = (float*)(smc + O_SC);
        #pragma unroll
        for (int n6 = 0; n6 < 3; ++n6){
            int kw0 = nq*24 + n6*8 + 2*tq;
            int qw0 = mt*16 + g;
            sc[(qw0  )*100 + kw0    ] = acc[n6][0];
            sc[(qw0  )*100 + kw0 + 1] = acc[n6][1];
            sc[(qw0+8)*100 + kw0    ] = acc[n6][2];
            sc[(qw0+8)*100 + kw0 + 1] = acc[n6][3];
        }
    }
    __syncthreads();   // (3) score visible; K reads done

    // ---- softmax over kw; attn planes into K area (4 rows per warp) ----
    {
        const float* sc = (const float*)(smc + O_SC);
        for (int r = warp*4; r < warp*4 + 4; ++r){
            const float* row = sc + r*100;
            float v0 = row[lane], v1 = row[lane+32], v2 = row[lane+64];
            float m = fmaxf(v0, fmaxf(v1, v2));
            #pragma unroll
            for (int o2 = 16; o2; o2 >>= 1) m = fmaxf(m, __shfl_xor_sync(0xffffffffu, m, o2));
            float e0 = __expf(v0 - m), e1 = __expf(v1 - m), e2 = __expf(v2 - m);
            float s = e0 + e1 + e2;
            #pragma unroll
            for (int o2 = 16; o2; o2 >>= 1) s += __shfl_xor_sync(0xffffffffu, s, o2);
            float inv = 1.0f / s;
            u16 hh, ll;
            split2(e0*inv, hh, ll);
            *(u16*)(smc + O_ATH + r*PL + (lane   )*2) = hh;
            *(u16*)(smc + O_ATL + r*PL + (lane   )*2) = ll;
            split2(e1*inv, hh, ll);
            *(u16*)(smc + O_ATH + r*PL + (lane+32)*2) = hh;
            *(u16*)(smc + O_ATL + r*PL + (lane+32)*2) = ll;
            split2(e2*inv, hh, ll);
            *(u16*)(smc + O_ATH + r*PL + (lane+64)*2) = hh;
            *(u16*)(smc + O_ATL + r*PL + (lane+64)*2) = ll;
        }
    }
    __syncthreads();   // (4) attn visible; score reads done

    // ---- AV: A=attn, B=vT -> out f32 [c][w] into XB area ----
    #pragma unroll
    for (int n6 = 0; n6 < 3; ++n6){
        acc[n6][0]=0.f; acc[n6][1]=0.f; acc[n6][2]=0.f; acc[n6][3]=0.f;
    }
    #pragma unroll
    for (int kt = 0; kt < 6; ++kt){
        u32 ah0,ah1,ah2,ah3, al0,al1,al2,al3;
        u32 h0,h1,h2,h3, g0,g1, l0,l1,l2,l3, m0,m1;
        LDSM4(ah0,ah1,ah2,ah3, sb + O_ATH + aOff + kt*32);
        LDSM4(al0,al1,al2,al3, sb + O_ATL + aOff + kt*32);
        LDSM4T(h0,h1,h2,h3, sb + O_VTH + bOff4 + (u32)(kt*16*PL));
        LDSM2T(g0,g1,       sb + O_VTH + bOff2 + (u32)(kt*16*PL));
        LDSM4T(l0,l1,l2,l3, sb + O_VTL + bOff4 + (u32)(kt*16*PL));
        LDSM2T(m0,m1,       sb + O_VTL + bOff2 + (u32)(kt*16*PL));
        kt_mma(acc, ah0,ah1,ah2,ah3, al0,al1,al2,al3,
               h0,h1,h2,h3,g0,g1, l0,l1,l2,l3,m0,m1);
    }
    {
        float* of = (float*)(smc + O_OF);   // XB area (score dead)
        #pragma unroll
        for (int n6 = 0; n6 < 3; ++n6){
            int c0  = nq*24 + n6*8 + 2*tq;
            int qw0 = mt*16 + g;
            of[(c0  )*100 + qw0    ] = acc[n6][0];
            of[(c0+1)*100 + qw0    ] = acc[n6][1];
            of[(c0  )*100 + qw0 + 8] = acc[n6][2];
            of[(c0+1)*100 + qw0 + 8] = acc[n6][3];
        }
    }
    __syncthreads();   // (5) out staging visible

    // ---- residual (re-read x) + coalesced writeout ----
    {
        const float* of = (const float*)(smc + O_OF);
        for (int idx = t; idx < CC*24; idx += NT){
            int c = idx/24, j = idx%24;
            float4 xv = *(const float4*)(x + base + (size_t)c*HWX + 4*j);
            float4 ov = *(const float4*)(of + c*100 + 4*j);
            ov.x += xv.x; ov.y += xv.y; ov.z += xv.z; ov.w += xv.w;
            *(float4*)(out + base + (size_t)c*HWX + 4*j) = ov;
        }
    }
}

extern "C" void kernel_launch(void* const* d_in, const int* in_sizes, int n_in,
                              void* d_out, int out_size){
    const float* x     = (const float*)d_in[0];
    const float* gam   = (const float*)d_in[1];
    const float* bet   = (const float*)d_in[2];
    const float* mn    = (const float*)d_in[3];
    const float* vr    = (const float*)d_in[4];
    const float* qkv_w = (const float*)d_in[5];
    const float* qkv_b = (const float*)d_in[6];
    float* out = (float*)d_out;

    cudaFuncSetAttribute(attn_kernel, cudaFuncAttributeMaxDynamicSharedMemorySize, SMEM_BYTES);

    prep_bias<<<OC, CC>>>(qkv_w, qkv_b, gam, bet, mn, vr);
    prep_frag<<<108, 32>>>(qkv_w, gam, vr);
    attn_kernel<<<BB*HH, NT, SMEM_BYTES>>>(x, out);
}

// round 13
// speedup vs baseline: 3.1579x; 1.0220x over previous
#include <cuda_runtime.h>
#include <cuda_bf16.h>
#include <cstdint>

#define BB 8
#define CC 96
#define HH 512
#define WW 96
#define HWX (HH*WW)     // 49152
#define OC  288
#define NT  768         // 24 warps
#define NROWS (BB*HH)   // 4096
#define GRID 152        // persistent: one CTA per SM

typedef unsigned int u32;
typedef unsigned short u16;

// prep outputs: W' (BN folded) in EXACT mma A-fragment order, hi/lo bf16 planes
// index: ((p*36 + mt*6 + kt)*32 + lane)*4 + q
__device__ u32   g_WfragH[108*32*4];
__device__ u32   g_WfragL[108*32*4];
__device__ float g_bias[OC];

// ---- smem map (bytes). bf16 planes: 96 rows x 104 b16 (stride 208B) ----
#define PL   208
#define PLSZ (96*PL)        // 19968
#define O_XBH 0             // x split hi [c][w]  (B for QKV; also residual source)
#define O_XBL (PLSZ)
#define O_QTH (2*PLSZ)      // qT hi [w][c]  (A for score)
#define O_QTL (3*PLSZ)
#define O_KH  (4*PLSZ)      // k hi [c][w]   (B for score) -> attn planes
#define O_KL  (5*PLSZ)
#define O_ATH (4*PLSZ)      // attn hi [qw][kw] (A for AV, reuse K)
#define O_ATL (5*PLSZ)
#define O_VTH (6*PLSZ)      // vT hi [w][c]  (B for AV)
#define O_VTL (7*PLSZ)
#define O_SC  (8*PLSZ)      // score f32 [qw][kw] stride 100 -> out f32 [c][w] staging
#define O_OF  (8*PLSZ)
#define SMEM_BYTES (8*PLSZ + 96*100*4)   // 159744 + 38400 = 198144

__device__ __forceinline__ u32 smem_u32(const void* p){
    u32 a; asm("{ .reg .u64 t; cvta.to.shared.u64 t, %1; cvt.u32.u64 %0, t; }" : "=r"(a) : "l"(p));
    return a;
}
#define LDSM4(r0,r1,r2,r3,addr) \
    asm volatile("ldmatrix.sync.aligned.m8n8.x4.shared.b16 {%0,%1,%2,%3}, [%4];" \
        : "=r"(r0),"=r"(r1),"=r"(r2),"=r"(r3) : "r"(addr))
#define LDSM4T(r0,r1,r2,r3,addr) \
    asm volatile("ldmatrix.sync.aligned.m8n8.x4.trans.shared.b16 {%0,%1,%2,%3}, [%4];" \
        : "=r"(r0),"=r"(r1),"=r"(r2),"=r"(r3) : "r"(addr))
#define LDSM2T(r0,r1,addr) \
    asm volatile("ldmatrix.sync.aligned.m8n8.x2.trans.shared.b16 {%0,%1}, [%2];" \
        : "=r"(r0),"=r"(r1) : "r"(addr))
#define MMA_BF16(d,a0,a1,a2,a3,b0,b1) \
    asm volatile("mma.sync.aligned.m16n8k16.row.col.f32.bf16.bf16.f32 " \
        "{%0,%1,%2,%3},{%4,%5,%6,%7},{%8,%9},{%0,%1,%2,%3};" \
        : "+f"((d)[0]),"+f"((d)[1]),"+f"((d)[2]),"+f"((d)[3]) \
        : "r"(a0),"r"(a1),"r"(a2),"r"(a3),"r"(b0),"r"(b1))

__device__ __forceinline__ void split2(float f, u16& h, u16& l){
    __nv_bfloat16 bh = __float2bfloat16_rn(f);
    float r = f - __bfloat162float(bh);
    __nv_bfloat16 bl = __float2bfloat16_rn(r);
    h = __bfloat16_as_ushort(bh); l = __bfloat16_as_ushort(bl);
}

// one k16 step for a 24-col quarter: 9 MMAs (hh, hl, lh), B frags passed in
__device__ __forceinline__ void kt_mma(float (&acc)[3][4],
        u32 ah0,u32 ah1,u32 ah2,u32 ah3,
        u32 al0,u32 al1,u32 al2,u32 al3,
        u32 h0,u32 h1,u32 h2,u32 h3,u32 g0,u32 g1,
        u32 l0,u32 l1,u32 l2,u32 l3,u32 m0,u32 m1){
    MMA_BF16(acc[0], ah0,ah1,ah2,ah3, h0,h1);
    MMA_BF16(acc[1], ah0,ah1,ah2,ah3, h2,h3);
    MMA_BF16(acc[2], ah0,ah1,ah2,ah3, g0,g1);
    MMA_BF16(acc[0], ah0,ah1,ah2,ah3, l0,l1);
    MMA_BF16(acc[1], ah0,ah1,ah2,ah3, l2,l3);
    MMA_BF16(acc[2], ah0,ah1,ah2,ah3, m0,m1);
    MMA_BF16(acc[0], al0,al1,al2,al3, h0,h1);
    MMA_BF16(acc[1], al0,al1,al2,al3, h2,h3);
    MMA_BF16(acc[2], al0,al1,al2,al3, g0,g1);
}

// ---------------- prep: bias ----------------
__global__ void prep_bias(const float* __restrict__ qkv_w, const float* __restrict__ qkv_b,
                          const float* __restrict__ gam, const float* __restrict__ bet,
                          const float* __restrict__ mn,  const float* __restrict__ vr){
    int o = blockIdx.x;
    int c = threadIdx.x;
    __shared__ float red[CC];
    float inv   = gam[c] * rsqrtf(vr[c] + 1e-5f);
    float shift = bet[c] - mn[c]*inv;
    red[c] = qkv_w[o*CC + c] * shift;
    __syncthreads();
    if (c < 32){
        float s = red[c] + red[c+32] + red[c+64];
        #pragma unroll
        for (int off = 16; off; off >>= 1) s += __shfl_down_sync(0xffffffffu, s, off);
        if (c == 0) g_bias[o] = s + qkv_b[o];
    }
}

// ---------------- prep: W' in A-fragment order ----------------
__global__ void prep_frag(const float* __restrict__ qkv_w,
                          const float* __restrict__ gam, const float* __restrict__ vr){
    int blk = blockIdx.x;          // 108 = p*36 + mt*6 + kt
    int p  = blk / 36;
    int mt = (blk / 6) % 6;
    int kt = blk % 6;
    int lane = threadIdx.x;        // 32
    int r  = lane >> 2;
    int c0 = 2*(lane & 3);
    int base = (blk*32 + lane)*4;
    #pragma unroll
    for (int q = 0; q < 4; ++q){
        int ro = mt*16 + r + (q & 1)*8;
        int co = kt*16 + c0 + (q >> 1)*8;
        float inv0 = gam[co]   * rsqrtf(vr[co]   + 1e-5f);
        float inv1 = gam[co+1] * rsqrtf(vr[co+1] + 1e-5f);
        u16 h0,l0,h1,l1;
        split2(qkv_w[(p*CC + ro)*CC + co]   * inv0, h0, l0);
        split2(qkv_w[(p*CC + ro)*CC + co+1] * inv1, h1, l1);
        g_WfragH[base + q] = (u32)h0 | ((u32)h1 << 16);
        g_WfragL[base + q] = (u32)l0 | ((u32)l1 << 16);
    }
}

// ---------------- fused attention kernel (persistent) ----------------
// 768 threads = 24 warps. warp = (mt, nq): mt = warp>>2, nq = warp&3 (24-col quarter).
__global__ __launch_bounds__(NT) void attn_kernel(const float* __restrict__ x,
                                                  float* __restrict__ out){
    extern __shared__ char smc[];
    const int t    = threadIdx.x;
    const int lane = t & 31;
    const int warp = t >> 5;     // 0..23
    const int mt = warp >> 2;    // 0..5
    const int nq = warp & 3;     // 0..3
    const int g  = lane >> 2;    // 0..7
    const int tq = lane & 3;     // 0..3

    // A-side (smem, x4) lane offset
    const int ai = lane >> 3, ar = lane & 7;
    const u32 aOff = (u32)((mt*16 + (ai&1)*8 + ar)*PL + ((ai>>1)*8)*2);
    // B-side lane offsets: x4-trans (16 cols) and x2-trans (last 8 cols)
    const u32 bRow  = (u32)(((lane & 7) + ((lane >> 3) & 1)*8)*PL);
    const u32 bOff4 = bRow + (u32)(nq*48 + ((lane >> 4)&1)*16);
    const u32 bOff2 = (u32)((((lane & 15) & 7) + (((lane & 15) >> 3))*8)*PL) + (u32)(nq*48 + 32);

    const u32 sb = smem_u32(smc);

    for (int bh = blockIdx.x; bh < NROWS; bh += GRID){
        const int b  = bh >> 9;
        const int h  = bh & 511;
        const size_t base = (size_t)b*CC*HWX + (size_t)h*WW;

        // ---- load x, split into XB planes [c][w] (planes live whole row) ----
        for (int idx = t; idx < CC*24; idx += NT){
            int c = idx/24, j = idx%24;
            float4 v = *(const float4*)(x + base + (size_t)c*HWX + 4*j);
            u16 hh[4], ll[4];
            split2(v.x, hh[0], ll[0]); split2(v.y, hh[1], ll[1]);
            split2(v.z, hh[2], ll[2]); split2(v.w, hh[3], ll[3]);
            u32 off = (u32)(c*PL + 8*j);
            *(u32*)(smc + O_XBH + off)     = (u32)hh[0] | ((u32)hh[1] << 16);
            *(u32*)(smc + O_XBH + off + 4) = (u32)hh[2] | ((u32)hh[3] << 16);
            *(u32*)(smc + O_XBL + off)     = (u32)ll[0] | ((u32)ll[1] << 16);
            *(u32*)(smc + O_XBL + off + 4) = (u32)ll[2] | ((u32)ll[3] << 16);
        }
        __syncthreads();   // (1) XB visible

        // ---- QKV: kt-outer, pass-inner; B fragments loaded ONCE per kt ----
        {
            float acc3[3][3][4];
            #pragma unroll
            for (int p = 0; p < 3; ++p){
                float bg  = g_bias[p*CC + mt*16 + g];
                float bg8 = g_bias[p*CC + mt*16 + g + 8];
                #pragma unroll
                for (int n6 = 0; n6 < 3; ++n6){
                    acc3[p][n6][0] = bg;  acc3[p][n6][1] = bg;
                    acc3[p][n6][2] = bg8; acc3[p][n6][3] = bg8;
                }
            }
            const u32* WfH = g_WfragH + (mt*6)*128 + lane*4;
            const u32* WfL = g_WfragL + (mt*6)*128 + lane*4;

            #pragma unroll
            for (int kt = 0; kt < 6; ++kt){
                u32 h0,h1,h2,h3, g0,g1, l0,l1,l2,l3, m0,m1;
                LDSM4T(h0,h1,h2,h3, sb + O_XBH + bOff4 + (u32)(kt*16*PL));
                LDSM2T(g0,g1,       sb + O_XBH + bOff2 + (u32)(kt*16*PL));
                LDSM4T(l0,l1,l2,l3, sb + O_XBL + bOff4 + (u32)(kt*16*PL));
                LDSM2T(m0,m1,       sb + O_XBL + bOff2 + (u32)(kt*16*PL));
                #pragma unroll
                for (int p = 0; p < 3; ++p){
                    uint4 AH = *(const uint4*)(WfH + (p*36 + kt)*128);
                    uint4 AL = *(const uint4*)(WfL + (p*36 + kt)*128);
                    kt_mma(acc3[p], AH.x,AH.y,AH.z,AH.w, AL.x,AL.y,AL.z,AL.w,
                           h0,h1,h2,h3,g0,g1, l0,l1,l2,l3,m0,m1);
                }
            }

            // epilogues -> split planes
            #pragma unroll
            for (int p = 0; p < 3; ++p){
                #pragma unroll
                for (int n6 = 0; n6 < 3; ++n6){
                    int w0 = nq*24 + n6*8 + 2*tq;
                    int o0 = mt*16 + g;
                    u16 h0,l0;
                    if (p == 1){
                        u16 h1,l1;
                        split2(acc3[p][n6][0], h0, l0); split2(acc3[p][n6][1], h1, l1);
                        *(u32*)(smc + O_KH + o0*PL + w0*2) = (u32)h0 | ((u32)h1 << 16);
                        *(u32*)(smc + O_KL + o0*PL + w0*2) = (u32)l0 | ((u32)l1 << 16);
                        split2(acc3[p][n6][2], h0, l0); split2(acc3[p][n6][3], h1, l1);
                        *(u32*)(smc + O_KH + (o0+8)*PL + w0*2) = (u32)h0 | ((u32)h1 << 16);
                        *(u32*)(smc + O_KL + (o0+8)*PL + w0*2) = (u32)l0 | ((u32)l1 << 16);
                    } else {
                        int OH = (p == 0) ? O_QTH : O_VTH;
                        int OL = (p == 0) ? O_QTL : O_VTL;
                        split2(acc3[p][n6][0], h0, l0);
                        *(u16*)(smc + OH + (w0  )*PL + o0*2) = h0;
                        *(u16*)(smc + OL + (w0  )*PL + o0*2) = l0;
                        split2(acc3[p][n6][1], h0, l0);
                        *(u16*)(smc + OH + (w0+1)*PL + o0*2) = h0;
                        *(u16*)(smc + OL + (w0+1)*PL + o0*2) = l0;
                        split2(acc3[p][n6][2], h0, l0);
                        *(u16*)(smc + OH + (w0  )*PL + (o0+8)*2) = h0;
                        *(u16*)(smc + OL + (w0  )*PL + (o0+8)*2) = l0;
                        split2(acc3[p][n6][3], h0, l0);
                        *(u16*)(smc + OH + (w0+1)*PL + (o0+8)*2) = h0;
                        *(u16*)(smc + OL + (w0+1)*PL + (o0+8)*2) = l0;
                    }
                }
            }
        }
        __syncthreads();   // (2) qT, k, vT visible

        float acc[3][4];

        // ---- score: A=qT (smem), B=k -> f32 into SC buffer ----
        #pragma unroll
        for (int n6 = 0; n6 < 3; ++n6){
            acc[n6][0]=0.f; acc[n6][1]=0.f; acc[n6][2]=0.f; acc[n6][3]=0.f;
        }
        #pragma unroll
        for (int kt = 0; kt < 6; ++kt){
            u32 ah0,ah1,ah2,ah3, al0,al1,al2,al3;
            u32 h0,h1,h2,h3, g0,g1, l0,l1,l2,l3, m0,m1;
            LDSM4(ah0,ah1,ah2,ah3, sb + O_QTH + aOff + kt*32);
            LDSM4(al0,al1,al2,al3, sb + O_QTL + aOff + kt*32);
            LDSM4T(h0,h1,h2,h3, sb + O_KH + bOff4 + (u32)(kt*16*PL));
            LDSM2T(g0,g1,       sb + O_KH + bOff2 + (u32)(kt*16*PL));
            LDSM4T(l0,l1,l2,l3, sb + O_KL + bOff4 + (u32)(kt*16*PL));
            LDSM2T(m0,m1,       sb + O_KL + bOff2 + (u32)(kt*16*PL));
            kt_mma(acc, ah0,ah1,ah2,ah3, al0,al1,al2,al3,
                   h0,h1,h2,h3,g0,g1, l0,l1,l2,l3,m0,m1);
        }
        {
            float* sc = (float*)(smc + O_SC);
            #pragma unroll
            for (int n6 = 0; n6 < 3; ++n6){
                int kw0 = nq*24 + n6*8 + 2*tq;
                int qw0 = mt*16 + g;
                sc[(qw0  )*100 + kw0    ] = acc[n6][0];
                sc[(qw0  )*100 + kw0 + 1] = acc[n6][1];
                sc[(qw0+8)*100 + kw0    ] = acc[n6][2];
                sc[(qw0+8)*100 + kw0 + 1] = acc[n6][3];
            }
        }
        __syncthreads();   // (3) score visible; qT/K reads done

        // ---- softmax over kw; attn planes into K area (4 rows per warp) ----
        {
            const float* sc = (const float*)(smc + O_SC);
            for (int r = warp*4; r < warp*4 + 4; ++r){
                const float* row = sc + r*100;
                float v0 = row[lane], v1 = row[lane+32], v2 = row[lane+64];
                float m = fmaxf(v0, fmaxf(v1, v2));
                #pragma unroll
                for (int o2 = 16; o2; o2 >>= 1) m = fmaxf(m, __shfl_xor_sync(0xffffffffu, m, o2));
                float e0 = __expf(v0 - m), e1 = __expf(v1 - m), e2 = __expf(v2 - m);
                float s = e0 + e1 + e2;
                #pragma unroll
                for (int o2 = 16; o2; o2 >>= 1) s += __shfl_xor_sync(0xffffffffu, s, o2);
                float inv = 1.0f / s;
                u16 hh, ll;
                split2(e0*inv, hh, ll);
                *(u16*)(smc + O_ATH + r*PL + (lane   )*2) = hh;
                *(u16*)(smc + O_ATL + r*PL + (lane   )*2) = ll;
                split2(e1*inv, hh, ll);
                *(u16*)(smc + O_ATH + r*PL + (lane+32)*2) = hh;
                *(u16*)(smc + O_ATL + r*PL + (lane+32)*2) = ll;
                split2(e2*inv, hh, ll);
                *(u16*)(smc + O_ATH + r*PL + (lane+64)*2) = hh;
                *(u16*)(smc + O_ATL + r*PL + (lane+64)*2) = ll;
            }
        }
        __syncthreads();   // (4) attn visible; score reads done

        // ---- AV: A=attn, B=vT -> out f32 [c][w] into OF (score dead) ----
        #pragma unroll
        for (int n6 = 0; n6 < 3; ++n6){
            acc[n6][0]=0.f; acc[n6][1]=0.f; acc[n6][2]=0.f; acc[n6][3]=0.f;
        }
        #pragma unroll
        for (int kt = 0; kt < 6; ++kt){
            u32 ah0,ah1,ah2,ah3, al0,al1,al2,al3;
            u32 h0,h1,h2,h3, g0,g1, l0,l1,l2,l3, m0,m1;
            LDSM4(ah0,ah1,ah2,ah3, sb + O_ATH + aOff + kt*32);
            LDSM4(al0,al1,al2,al3, sb + O_ATL + aOff + kt*32);
            LDSM4T(h0,h1,h2,h3, sb + O_VTH + bOff4 + (u32)(kt*16*PL));
            LDSM2T(g0,g1,       sb + O_VTH + bOff2 + (u32)(kt*16*PL));
            LDSM4T(l0,l1,l2,l3, sb + O_VTL + bOff4 + (u32)(kt*16*PL));
            LDSM2T(m0,m1,       sb + O_VTL + bOff2 + (u32)(kt*16*PL));
            kt_mma(acc, ah0,ah1,ah2,ah3, al0,al1,al2,al3,
                   h0,h1,h2,h3,g0,g1, l0,l1,l2,l3,m0,m1);
        }
        {
            float* of = (float*)(smc + O_OF);
            #pragma unroll
            for (int n6 = 0; n6 < 3; ++n6){
                int c0  = nq*24 + n6*8 + 2*tq;
                int qw0 = mt*16 + g;
                of[(c0  )*100 + qw0    ] = acc[n6][0];
                of[(c0+1)*100 + qw0    ] = acc[n6][1];
                of[(c0  )*100 + qw0 + 8] = acc[n6][2];
                of[(c0+1)*100 + qw0 + 8] = acc[n6][3];
            }
        }
        __syncthreads();   // (5) out staging visible

        // ---- residual from XB planes (x ≈ hi+lo) + coalesced writeout ----
        {
            const float* of = (const float*)(smc + O_OF);
            for (int idx = t; idx < CC*24; idx += NT){
                int c = idx/24, j = idx%24;
                float4 ov = *(const float4*)(of + c*100 + 4*j);
                u32 off = (u32)(c*PL + 8*j);
                __nv_bfloat162 h01 = *(__nv_bfloat162*)(smc + O_XBH + off);
                __nv_bfloat162 h23 = *(__nv_bfloat162*)(smc + O_XBH + off + 4);
                __nv_bfloat162 l01 = *(__nv_bfloat162*)(smc + O_XBL + off);
                __nv_bfloat162 l23 = *(__nv_bfloat162*)(smc + O_XBL + off + 4);
                float2 fh01 = __bfloat1622float2(h01);
                float2 fh23 = __bfloat1622float2(h23);
                float2 fl01 = __bfloat1622float2(l01);
                float2 fl23 = __bfloat1622float2(l23);
                ov.x += fh01.x + fl01.x;
                ov.y += fh01.y + fl01.y;
                ov.z += fh23.x + fl23.x;
                ov.w += fh23.y + fl23.y;
                *(float4*)(out + base + (size_t)c*HWX + 4*j) = ov;
            }
        }
        __syncthreads();   // (6) row done; XB/OF reusable next iteration
    }
}

extern "C" void kernel_launch(void* const* d_in, const int* in_sizes, int n_in,
                              void* d_out, int out_size){
    const float* x     = (const float*)d_in[0];
    const float* gam   = (const float*)d_in[1];
    const float* bet   = (const float*)d_in[2];
    const float* mn    = (const float*)d_in[3];
    const float* vr    = (const float*)d_in[4];
    const float* qkv_w = (const float*)d_in[5];
    const float* qkv_b = (const float*)d_in[6];
    float* out = (float*)d_out;

    cudaFuncSetAttribute(attn_kernel, cudaFuncAttributeMaxDynamicSharedMemorySize, SMEM_BYTES);

    prep_bias<<<OC, CC>>>(qkv_w, qkv_b, gam, bet, mn, vr);
    prep_frag<<<108, 32>>>(qkv_w, gam, vr);
    attn_kernel<<<GRID, NT, SMEM_BYTES>>>(x, out);
}

// round 14
// speedup vs baseline: 3.8158x; 1.2083x over previous
#include <cuda_runtime.h>
#include <cuda_bf16.h>
#include <cstdint>

#define BB 8
#define CC 96
#define HH 512
#define WW 96
#define HWX (HH*WW)     // 49152
#define OC  288
#define NT  768         // 24 warps
#define NROWS (BB*HH)   // 4096
#define GRID 152        // persistent: one CTA per SM

typedef unsigned int u32;
typedef unsigned short u16;

// prep outputs: W' (BN folded) in EXACT mma A-fragment order, hi/lo bf16 planes
__device__ u32   g_WfragH[108*32*4];
__device__ u32   g_WfragL[108*32*4];
__device__ float g_bias[OC];

// ---- smem map (bytes). bf16 planes: 96 rows x 104 b16 (stride 208B) ----
#define PL   208
#define PLSZ (96*PL)        // 19968
#define O_XBH 0             // x split hi [c][w] (B for QKV; residual source)
#define O_XBL (PLSZ)
#define O_QTH (2*PLSZ)      // qT hi [w][c]  (A for score)
#define O_QTL (3*PLSZ)
#define O_OF  (2*PLSZ)      // out f32 [c][w] stride 100 (qT area, dead after score)
#define O_KH  (4*PLSZ)      // k hi [c][w]   (B for score)
#define O_KL  (5*PLSZ)
#define O_ATH (4*PLSZ)      // attn hi [qw][kw] (K area, safe after barrier 3)
#define O_ATL (5*PLSZ)
#define O_VTH (6*PLSZ)      // vT hi [w][c]  (B for AV)
#define O_VTL (7*PLSZ)
#define O_PM  (8*PLSZ)      // softmax partials [96][4] float2 = 3072 B
#define O_XST (8*PLSZ + 3072)  // next-row x staging (raw f32): 36864 B
#define SMEM_BYTES (O_XST + 36864)   // 199680

__device__ __forceinline__ u32 smem_u32(const void* p){
    u32 a; asm("{ .reg .u64 t; cvta.to.shared.u64 t, %1; cvt.u32.u64 %0, t; }" : "=r"(a) : "l"(p));
    return a;
}
#define LDSM4(r0,r1,r2,r3,addr) \
    asm volatile("ldmatrix.sync.aligned.m8n8.x4.shared.b16 {%0,%1,%2,%3}, [%4];" \
        : "=r"(r0),"=r"(r1),"=r"(r2),"=r"(r3) : "r"(addr))
#define LDSM4T(r0,r1,r2,r3,addr) \
    asm volatile("ldmatrix.sync.aligned.m8n8.x4.trans.shared.b16 {%0,%1,%2,%3}, [%4];" \
        : "=r"(r0),"=r"(r1),"=r"(r2),"=r"(r3) : "r"(addr))
#define LDSM2T(r0,r1,addr) \
    asm volatile("ldmatrix.sync.aligned.m8n8.x2.trans.shared.b16 {%0,%1}, [%2];" \
        : "=r"(r0),"=r"(r1) : "r"(addr))
#define MMA_BF16(d,a0,a1,a2,a3,b0,b1) \
    asm volatile("mma.sync.aligned.m16n8k16.row.col.f32.bf16.bf16.f32 " \
        "{%0,%1,%2,%3},{%4,%5,%6,%7},{%8,%9},{%0,%1,%2,%3};" \
        : "+f"((d)[0]),"+f"((d)[1]),"+f"((d)[2]),"+f"((d)[3]) \
        : "r"(a0),"r"(a1),"r"(a2),"r"(a3),"r"(b0),"r"(b1))
#define NBAR(id) asm volatile("bar.sync %0, 128;" :: "r"(id) : "memory")
__device__ __forceinline__ void cp_async16(u32 dst, const void* src){
    asm volatile("cp.async.cg.shared.global [%0], [%1], 16;" :: "r"(dst), "l"(src));
}
#define CP_COMMIT() asm volatile("cp.async.commit_group;" ::: "memory")
#define CP_WAIT0()  asm volatile("cp.async.wait_group 0;" ::: "memory")

__device__ __forceinline__ void split2(float f, u16& h, u16& l){
    __nv_bfloat16 bh = __float2bfloat16_rn(f);
    float r = f - __bfloat162float(bh);
    __nv_bfloat16 bl = __float2bfloat16_rn(r);
    h = __bfloat16_as_ushort(bh); l = __bfloat16_as_ushort(bl);
}

// one k16 step for a 24-col quarter: 9 MMAs (hh, hl, lh), B frags passed in
__device__ __forceinline__ void kt_mma(float (&acc)[3][4],
        u32 ah0,u32 ah1,u32 ah2,u32 ah3,
        u32 al0,u32 al1,u32 al2,u32 al3,
        u32 h0,u32 h1,u32 h2,u32 h3,u32 g0,u32 g1,
        u32 l0,u32 l1,u32 l2,u32 l3,u32 m0,u32 m1){
    MMA_BF16(acc[0], ah0,ah1,ah2,ah3, h0,h1);
    MMA_BF16(acc[1], ah0,ah1,ah2,ah3, h2,h3);
    MMA_BF16(acc[2], ah0,ah1,ah2,ah3, g0,g1);
    MMA_BF16(acc[0], ah0,ah1,ah2,ah3, l0,l1);
    MMA_BF16(acc[1], ah0,ah1,ah2,ah3, l2,l3);
    MMA_BF16(acc[2], ah0,ah1,ah2,ah3, m0,m1);
    MMA_BF16(acc[0], al0,al1,al2,al3, h0,h1);
    MMA_BF16(acc[1], al0,al1,al2,al3, h2,h3);
    MMA_BF16(acc[2], al0,al1,al2,al3, g0,g1);
}

// ---------------- prep: bias ----------------
__global__ void prep_bias(const float* __restrict__ qkv_w, const float* __restrict__ qkv_b,
                          const float* __restrict__ gam, const float* __restrict__ bet,
                          const float* __restrict__ mn,  const float* __restrict__ vr){
    int o = blockIdx.x;
    int c = threadIdx.x;
    __shared__ float red[CC];
    float inv   = gam[c] * rsqrtf(vr[c] + 1e-5f);
    float shift = bet[c] - mn[c]*inv;
    red[c] = qkv_w[o*CC + c] * shift;
    __syncthreads();
    if (c < 32){
        float s = red[c] + red[c+32] + red[c+64];
        #pragma unroll
        for (int off = 16; off; off >>= 1) s += __shfl_down_sync(0xffffffffu, s, off);
        if (c == 0) g_bias[o] = s + qkv_b[o];
    }
}

// ---------------- prep: W' in A-fragment order ----------------
__global__ void prep_frag(const float* __restrict__ qkv_w,
                          const float* __restrict__ gam, const float* __restrict__ vr){
    int blk = blockIdx.x;          // 108 = p*36 + mt*6 + kt
    int p  = blk / 36;
    int mt = (blk / 6) % 6;
    int kt = blk % 6;
    int lane = threadIdx.x;
    int r  = lane >> 2;
    int c0 = 2*(lane & 3);
    int base = (blk*32 + lane)*4;
    #pragma unroll
    for (int q = 0; q < 4; ++q){
        int ro = mt*16 + r + (q & 1)*8;
        int co = kt*16 + c0 + (q >> 1)*8;
        float inv0 = gam[co]   * rsqrtf(vr[co]   + 1e-5f);
        float inv1 = gam[co+1] * rsqrtf(vr[co+1] + 1e-5f);
        u16 h0,l0,h1,l1;
        split2(qkv_w[(p*CC + ro)*CC + co]   * inv0, h0, l0);
        split2(qkv_w[(p*CC + ro)*CC + co+1] * inv1, h1, l1);
        g_WfragH[base + q] = (u32)h0 | ((u32)h1 << 16);
        g_WfragL[base + q] = (u32)l0 | ((u32)l1 << 16);
    }
}

// ---------------- fused attention kernel (persistent, prefetch, reg-softmax) ----------------
__global__ __launch_bounds__(NT) void attn_kernel(const float* __restrict__ x,
                                                  float* __restrict__ out){
    extern __shared__ char smc[];
    const int t    = threadIdx.x;
    const int lane = t & 31;
    const int warp = t >> 5;     // 0..23
    const int mt = warp >> 2;    // 0..5
    const int nq = warp & 3;     // 0..3
    const int g  = lane >> 2;    // 0..7
    const int tq = lane & 3;     // 0..3

    const int ai = lane >> 3, ar = lane & 7;
    const u32 aOff = (u32)((mt*16 + (ai&1)*8 + ar)*PL + ((ai>>1)*8)*2);
    const u32 bRow  = (u32)(((lane & 7) + ((lane >> 3) & 1)*8)*PL);
    const u32 bOff4 = bRow + (u32)(nq*48 + ((lane >> 4)&1)*16);
    const u32 bOff2 = (u32)((((lane & 15) & 7) + (((lane & 15) >> 3))*8)*PL) + (u32)(nq*48 + 32);

    const u32 sb = smem_u32(smc);
    const int qw0 = mt*16 + g;

    // ---- prefetch first row into XSTAGE ----
    {
        const int bh0 = blockIdx.x;
        const size_t basep = (size_t)(bh0 >> 9)*CC*HWX + (size_t)(bh0 & 511)*WW;
        for (int idx = t; idx < CC*24; idx += NT){
            int c = idx/24, j = idx%24;
            cp_async16(sb + O_XST + (u32)idx*16, x + basep + (size_t)c*HWX + 4*j);
        }
        CP_COMMIT();
    }

    for (int bh = blockIdx.x; bh < NROWS; bh += GRID){
        const size_t base = (size_t)(bh >> 9)*CC*HWX + (size_t)(bh & 511)*WW;

        // ---- consume staged x: split into XB planes [c][w] ----
        CP_WAIT0();
        for (int idx = t; idx < CC*24; idx += NT){
            int c = idx/24, j = idx%24;
            float4 v = *(const float4*)(smc + O_XST + idx*16);
            u16 hh[4], ll[4];
            split2(v.x, hh[0], ll[0]); split2(v.y, hh[1], ll[1]);
            split2(v.z, hh[2], ll[2]); split2(v.w, hh[3], ll[3]);
            u32 off = (u32)(c*PL + 8*j);
            *(u32*)(smc + O_XBH + off)     = (u32)hh[0] | ((u32)hh[1] << 16);
            *(u32*)(smc + O_XBH + off + 4) = (u32)hh[2] | ((u32)hh[3] << 16);
            *(u32*)(smc + O_XBL + off)     = (u32)ll[0] | ((u32)ll[1] << 16);
            *(u32*)(smc + O_XBL + off + 4) = (u32)ll[2] | ((u32)ll[3] << 16);
        }
        __syncthreads();   // (1) XB visible

        // ---- QKV: kt-outer, pass-inner; B fragments loaded ONCE per kt ----
        {
            float acc3[3][3][4];
            #pragma unroll
            for (int p = 0; p < 3; ++p){
                float bg  = g_bias[p*CC + qw0];
                float bg8 = g_bias[p*CC + qw0 + 8];
                #pragma unroll
                for (int n6 = 0; n6 < 3; ++n6){
                    acc3[p][n6][0] = bg;  acc3[p][n6][1] = bg;
                    acc3[p][n6][2] = bg8; acc3[p][n6][3] = bg8;
                }
            }
            const u32* WfH = g_WfragH + (mt*6)*128 + lane*4;
            const u32* WfL = g_WfragL + (mt*6)*128 + lane*4;

            #pragma unroll
            for (int kt = 0; kt < 6; ++kt){
                u32 h0,h1,h2,h3, g0,g1, l0,l1,l2,l3, m0,m1;
                LDSM4T(h0,h1,h2,h3, sb + O_XBH + bOff4 + (u32)(kt*16*PL));
                LDSM2T(g0,g1,       sb + O_XBH + bOff2 + (u32)(kt*16*PL));
                LDSM4T(l0,l1,l2,l3, sb + O_XBL + bOff4 + (u32)(kt*16*PL));
                LDSM2T(m0,m1,       sb + O_XBL + bOff2 + (u32)(kt*16*PL));
                #pragma unroll
                for (int p = 0; p < 3; ++p){
                    uint4 AH = *(const uint4*)(WfH + (p*36 + kt)*128);
                    uint4 AL = *(const uint4*)(WfL + (p*36 + kt)*128);
                    kt_mma(acc3[p], AH.x,AH.y,AH.z,AH.w, AL.x,AL.y,AL.z,AL.w,
                           h0,h1,h2,h3,g0,g1, l0,l1,l2,l3,m0,m1);
                }
            }

            // epilogues -> split planes
            #pragma unroll
            for (int p = 0; p < 3; ++p){
                #pragma unroll
                for (int n6 = 0; n6 < 3; ++n6){
                    int w0 = nq*24 + n6*8 + 2*tq;
                    int o0 = qw0;
                    u16 h0,l0;
                    if (p == 1){
                        u16 h1,l1;
                        split2(acc3[p][n6][0], h0, l0); split2(acc3[p][n6][1], h1, l1);
                        *(u32*)(smc + O_KH + o0*PL + w0*2) = (u32)h0 | ((u32)h1 << 16);
                        *(u32*)(smc + O_KL + o0*PL + w0*2) = (u32)l0 | ((u32)l1 << 16);
                        split2(acc3[p][n6][2], h0, l0); split2(acc3[p][n6][3], h1, l1);
                        *(u32*)(smc + O_KH + (o0+8)*PL + w0*2) = (u32)h0 | ((u32)h1 << 16);
                        *(u32*)(smc + O_KL + (o0+8)*PL + w0*2) = (u32)l0 | ((u32)l1 << 16);
                    } else {
                        int OH = (p == 0) ? O_QTH : O_VTH;
                        int OL = (p == 0) ? O_QTL : O_VTL;
                        split2(acc3[p][n6][0], h0, l0);
                        *(u16*)(smc + OH + (w0  )*PL + o0*2) = h0;
                        *(u16*)(smc + OL + (w0  )*PL + o0*2) = l0;
                        split2(acc3[p][n6][1], h0, l0);
                        *(u16*)(smc + OH + (w0+1)*PL + o0*2) = h0;
                        *(u16*)(smc + OL + (w0+1)*PL + o0*2) = l0;
                        split2(acc3[p][n6][2], h0, l0);
                        *(u16*)(smc + OH + (w0  )*PL + (o0+8)*2) = h0;
                        *(u16*)(smc + OL + (w0  )*PL + (o0+8)*2) = l0;
                        split2(acc3[p][n6][3], h0, l0);
                        *(u16*)(smc + OH + (w0+1)*PL + (o0+8)*2) = h0;
                        *(u16*)(smc + OL + (w0+1)*PL + (o0+8)*2) = l0;
                    }
                }
            }
        }
        __syncthreads();   // (2) qT, k, vT visible; XSTAGE reads done

        // ---- prefetch next row into XSTAGE (hidden behind score/softmax/AV) ----
        {
            int nxt = bh + GRID;
            if (nxt < NROWS){
                const size_t basep = (size_t)(nxt >> 9)*CC*HWX + (size_t)(nxt & 511)*WW;
                for (int idx = t; idx < CC*24; idx += NT){
                    int c = idx/24, j = idx%24;
                    cp_async16(sb + O_XST + (u32)idx*16, x + basep + (size_t)c*HWX + 4*j);
                }
                CP_COMMIT();
            }
        }

        float acc[3][4];

        // ---- score: A=qT (smem), B=k; result stays in registers ----
        #pragma unroll
        for (int n6 = 0; n6 < 3; ++n6){
            acc[n6][0]=0.f; acc[n6][1]=0.f; acc[n6][2]=0.f; acc[n6][3]=0.f;
        }
        #pragma unroll
        for (int kt = 0; kt < 6; ++kt){
            u32 ah0,ah1,ah2,ah3, al0,al1,al2,al3;
            u32 h0,h1,h2,h3, g0,g1, l0,l1,l2,l3, m0,m1;
            LDSM4(ah0,ah1,ah2,ah3, sb + O_QTH + aOff + kt*32);
            LDSM4(al0,al1,al2,al3, sb + O_QTL + aOff + kt*32);
            LDSM4T(h0,h1,h2,h3, sb + O_KH + bOff4 + (u32)(kt*16*PL));
            LDSM2T(g0,g1,       sb + O_KH + bOff2 + (u32)(kt*16*PL));
            LDSM4T(l0,l1,l2,l3, sb + O_KL + bOff4 + (u32)(kt*16*PL));
            LDSM2T(m0,m1,       sb + O_KL + bOff2 + (u32)(kt*16*PL));
            kt_mma(acc, ah0,ah1,ah2,ah3, al0,al1,al2,al3,
                   h0,h1,h2,h3,g0,g1, l0,l1,l2,l3,m0,m1);
        }

        // ---- register softmax, stage 1: per-warp partials over 24 kw cols ----
        float eA[6], eB[6], mA, mB, sA, sB;
        {
            mA = fmaxf(fmaxf(fmaxf(acc[0][0],acc[0][1]), fmaxf(acc[1][0],acc[1][1])),
                       fmaxf(acc[2][0],acc[2][1]));
            mB = fmaxf(fmaxf(fmaxf(acc[0][2],acc[0][3]), fmaxf(acc[1][2],acc[1][3])),
                       fmaxf(acc[2][2],acc[2][3]));
            mA = fmaxf(mA, __shfl_xor_sync(0xffffffffu, mA, 1));
            mA = fmaxf(mA, __shfl_xor_sync(0xffffffffu, mA, 2));
            mB = fmaxf(mB, __shfl_xor_sync(0xffffffffu, mB, 1));
            mB = fmaxf(mB, __shfl_xor_sync(0xffffffffu, mB, 2));
            sA = 0.f; sB = 0.f;
            #pragma unroll
            for (int n6 = 0; n6 < 3; ++n6){
                eA[2*n6  ] = __expf(acc[n6][0] - mA); sA += eA[2*n6  ];
                eA[2*n6+1] = __expf(acc[n6][1] - mA); sA += eA[2*n6+1];
                eB[2*n6  ] = __expf(acc[n6][2] - mB); sB += eB[2*n6  ];
                eB[2*n6+1] = __expf(acc[n6][3] - mB); sB += eB[2*n6+1];
            }
            sA += __shfl_xor_sync(0xffffffffu, sA, 1);
            sA += __shfl_xor_sync(0xffffffffu, sA, 2);
            sB += __shfl_xor_sync(0xffffffffu, sB, 1);
            sB += __shfl_xor_sync(0xffffffffu, sB, 2);
            if (tq == 0){
                *(float2*)(smc + O_PM + (qw0  )*32 + nq*8) = make_float2(mA, sA);
                *(float2*)(smc + O_PM + (qw0+8)*32 + nq*8) = make_float2(mB, sB);
            }
        }
        __syncthreads();   // (3) partials visible; ALL qT/K reads done CTA-wide

        // ---- softmax stage 2: combine, write attn planes into K area ----
        {
            float4 a0 = *(const float4*)(smc + O_PM + (qw0  )*32);
            float4 a1 = *(const float4*)(smc + O_PM + (qw0  )*32 + 16);
            float4 b0 = *(const float4*)(smc + O_PM + (qw0+8)*32);
            float4 b1 = *(const float4*)(smc + O_PM + (qw0+8)*32 + 16);
            float MA = fmaxf(fmaxf(a0.x, a0.z), fmaxf(a1.x, a1.z));
            float MB = fmaxf(fmaxf(b0.x, b0.z), fmaxf(b1.x, b1.z));
            float SA = a0.y*__expf(a0.x-MA) + a0.w*__expf(a0.z-MA)
                     + a1.y*__expf(a1.x-MA) + a1.w*__expf(a1.z-MA);
            float SB = b0.y*__expf(b0.x-MB) + b0.w*__expf(b0.z-MB)
                     + b1.y*__expf(b1.x-MB) + b1.w*__expf(b1.z-MB);
            float fA = __expf(mA - MA) / SA;
            float fB = __expf(mB - MB) / SB;
            #pragma unroll
            for (int n6 = 0; n6 < 3; ++n6){
                int kw0 = nq*24 + n6*8 + 2*tq;
                u16 h0,l0,h1,l1;
                split2(eA[2*n6]*fA, h0, l0); split2(eA[2*n6+1]*fA, h1, l1);
                *(u32*)(smc + O_ATH + (qw0  )*PL + kw0*2) = (u32)h0 | ((u32)h1 << 16);
                *(u32*)(smc + O_ATL + (qw0  )*PL + kw0*2) = (u32)l0 | ((u32)l1 << 16);
                split2(eB[2*n6]*fB, h0, l0); split2(eB[2*n6+1]*fB, h1, l1);
                *(u32*)(smc + O_ATH + (qw0+8)*PL + kw0*2) = (u32)h0 | ((u32)h1 << 16);
                *(u32*)(smc + O_ATL + (qw0+8)*PL + kw0*2) = (u32)l0 | ((u32)l1 << 16);
            }
        }
        NBAR(mt + 1);      // (4) attn rows [16mt,16mt+16) complete within mt-group

        // ---- AV: A=attn, B=vT -> out f32 [c][w] into OF (qT area) ----
        #pragma unroll
        for (int n6 = 0; n6 < 3; ++n6){
            acc[n6][0]=0.f; acc[n6][1]=0.f; acc[n6][2]=0.f; acc[n6][3]=0.f;
        }
        #pragma unroll
        for (int kt = 0; kt < 6; ++kt){
            u32 ah0,ah1,ah2,ah3, al0,al1,al2,al3;
            u32 h0,h1,h2,h3, g0,g1, l0,l1,l2,l3, m0,m1;
            LDSM4(ah0,ah1,ah2,ah3, sb + O_ATH + aOff + kt*32);
            LDSM4(al0,al1,al2,al3, sb + O_ATL + aOff + kt*32);
            LDSM4T(h0,h1,h2,h3, sb + O_VTH + bOff4 + (u32)(kt*16*PL));
            LDSM2T(g0,g1,       sb + O_VTH + bOff2 + (u32)(kt*16*PL));
            LDSM4T(l0,l1,l2,l3, sb + O_VTL + bOff4 + (u32)(kt*16*PL));
            LDSM2T(m0,m1,       sb + O_VTL + bOff2 + (u32)(kt*16*PL));
            kt_mma(acc, ah0,ah1,ah2,ah3, al0,al1,al2,al3,
                   h0,h1,h2,h3,g0,g1, l0,l1,l2,l3,m0,m1);
        }
        {
            float* of = (float*)(smc + O_OF);
            #pragma unroll
            for (int n6 = 0; n6 < 3; ++n6){
                int c0 = nq*24 + n6*8 + 2*tq;
                of[(c0  )*100 + qw0    ] = acc[n6][0];
                of[(c0+1)*100 + qw0    ] = acc[n6][1];
                of[(c0  )*100 + qw0 + 8] = acc[n6][2];
                of[(c0+1)*100 + qw0 + 8] = acc[n6][3];
            }
        }
        __syncthreads();   // (5) out staging visible

        // ---- residual from XB planes (x ≈ hi+lo) + coalesced writeout ----
        {
            const float* of = (const float*)(smc + O_OF);
            for (int idx = t; idx < CC*24; idx += NT){
                int c = idx/24, j = idx%24;
                float4 ov = *(const float4*)(of + c*100 + 4*j);
                u32 off = (u32)(c*PL + 8*j);
                __nv_bfloat162 h01 = *(__nv_bfloat162*)(smc + O_XBH + off);
                __nv_bfloat162 h23 = *(__nv_bfloat162*)(smc + O_XBH + off + 4);
                __nv_bfloat162 l01 = *(__nv_bfloat162*)(smc + O_XBL + off);
                __nv_bfloat162 l23 = *(__nv_bfloat162*)(smc + O_XBL + off + 4);
                float2 fh01 = __bfloat1622float2(h01);
                float2 fh23 = __bfloat1622float2(h23);
                float2 fl01 = __bfloat1622float2(l01);
                float2 fl23 = __bfloat1622float2(l23);
                ov.x += fh01.x + fl01.x;
                ov.y += fh01.y + fl01.y;
                ov.z += fh23.x + fl23.x;
                ov.w += fh23.y + fl23.y;
                *(float4*)(out + base + (size_t)c*HWX + 4*j) = ov;
            }
        }
        __syncthreads();   // (6) row done; planes reusable next iteration
    }
}

extern "C" void kernel_launch(void* const* d_in, const int* in_sizes, int n_in,
                              void* d_out, int out_size){
    const float* x     = (const float*)d_in[0];
    const float* gam   = (const float*)d_in[1];
    const float* bet   = (const float*)d_in[2];
    const float* mn    = (const float*)d_in[3];
    const float* vr    = (const float*)d_in[4];
    const float* qkv_w = (const float*)d_in[5];
    const float* qkv_b = (const float*)d_in[6];
    float* out = (float*)d_out;

    cudaFuncSetAttribute(attn_kernel, cudaFuncAttributeMaxDynamicSharedMemorySize, SMEM_BYTES);

    prep_bias<<<OC, CC>>>(qkv_w, qkv_b, gam, bet, mn, vr);
    prep_frag<<<108, 32>>>(qkv_w, gam, vr);
    attn_kernel<<<GRID, NT, SMEM_BYTES>>>(x, out);
}

// round 15
// speedup vs baseline: 4.1218x; 1.0802x over previous
#include <cuda_runtime.h>
#include <cuda_bf16.h>
#include <cuda_fp16.h>
#include <cstdint>

#define BB 8
#define CC 96
#define HH 512
#define WW 96
#define HWX (HH*WW)     // 49152
#define OC  288
#define NT  768         // 24 warps
#define NROWS (BB*HH)   // 4096
#define GRID 152        // persistent: one CTA per SM

typedef unsigned int u32;
typedef unsigned short u16;

// prep outputs: W' (BN folded) in EXACT mma A-fragment order, hi/lo bf16 planes
__device__ u32   g_WfragH[108*32*4];
__device__ u32   g_WfragL[108*32*4];
__device__ float g_bias[OC];

// ---- smem map (bytes). 16-bit planes: 96 rows x 104 elems (stride 208B) ----
#define PL   208
#define PLSZ (96*PL)        // 19968
#define O_XBH 0             // x split hi [c][w] (B for QKV; residual source)
#define O_XBL (PLSZ)
#define O_QTH (2*PLSZ)      // qT hi [w][c]  (A for score)
#define O_QTL (3*PLSZ)
#define O_OF  (2*PLSZ)      // out f32 [c][w] stride 100 (qT area, dead after score)
#define O_KH  (4*PLSZ)      // k hi [c][w]   (B for score)
#define O_KL  (5*PLSZ)
#define O_ATH (4*PLSZ)      // attn fp16 [qw][kw] (K area, safe after barrier 3)
#define O_VTH (6*PLSZ)      // vT fp16 hi [w][c]  (B for AV)
#define O_VTL (7*PLSZ)      // vT fp16 lo
#define O_PM  (8*PLSZ)      // softmax partials [96][4] float2 = 3072 B
#define O_XST (8*PLSZ + 3072)  // next-row x staging (raw f32): 36864 B
#define SMEM_BYTES (O_XST + 36864)   // 199680

__device__ __forceinline__ u32 smem_u32(const void* p){
    u32 a; asm("{ .reg .u64 t; cvta.to.shared.u64 t, %1; cvt.u32.u64 %0, t; }" : "=r"(a) : "l"(p));
    return a;
}
#define LDSM4(r0,r1,r2,r3,addr) \
    asm volatile("ldmatrix.sync.aligned.m8n8.x4.shared.b16 {%0,%1,%2,%3}, [%4];" \
        : "=r"(r0),"=r"(r1),"=r"(r2),"=r"(r3) : "r"(addr))
#define LDSM4T(r0,r1,r2,r3,addr) \
    asm volatile("ldmatrix.sync.aligned.m8n8.x4.trans.shared.b16 {%0,%1,%2,%3}, [%4];" \
        : "=r"(r0),"=r"(r1),"=r"(r2),"=r"(r3) : "r"(addr))
#define LDSM2T(r0,r1,addr) \
    asm volatile("ldmatrix.sync.aligned.m8n8.x2.trans.shared.b16 {%0,%1}, [%2];" \
        : "=r"(r0),"=r"(r1) : "r"(addr))
#define MMA_BF16(d,a0,a1,a2,a3,b0,b1) \
    asm volatile("mma.sync.aligned.m16n8k16.row.col.f32.bf16.bf16.f32 " \
        "{%0,%1,%2,%3},{%4,%5,%6,%7},{%8,%9},{%0,%1,%2,%3};" \
        : "+f"((d)[0]),"+f"((d)[1]),"+f"((d)[2]),"+f"((d)[3]) \
        : "r"(a0),"r"(a1),"r"(a2),"r"(a3),"r"(b0),"r"(b1))
#define MMA_F16(d,a0,a1,a2,a3,b0,b1) \
    asm volatile("mma.sync.aligned.m16n8k16.row.col.f32.f16.f16.f32 " \
        "{%0,%1,%2,%3},{%4,%5,%6,%7},{%8,%9},{%0,%1,%2,%3};" \
        : "+f"((d)[0]),"+f"((d)[1]),"+f"((d)[2]),"+f"((d)[3]) \
        : "r"(a0),"r"(a1),"r"(a2),"r"(a3),"r"(b0),"r"(b1))
#define NBAR(id) asm volatile("bar.sync %0, 128;" :: "r"(id) : "memory")
__device__ __forceinline__ void cp_async16(u32 dst, const void* src){
    asm volatile("cp.async.cg.shared.global [%0], [%1], 16;" :: "r"(dst), "l"(src));
}
#define CP_COMMIT() asm volatile("cp.async.commit_group;" ::: "memory")
#define CP_WAIT0()  asm volatile("cp.async.wait_group 0;" ::: "memory")

__device__ __forceinline__ void split2(float f, u16& h, u16& l){
    __nv_bfloat16 bh = __float2bfloat16_rn(f);
    float r = f - __bfloat162float(bh);
    __nv_bfloat16 bl = __float2bfloat16_rn(r);
    h = __bfloat16_as_ushort(bh); l = __bfloat16_as_ushort(bl);
}
__device__ __forceinline__ void split2h(float f, u16& h, u16& l){
    __half hh = __float2half_rn(f);
    float r = f - __half2float(hh);
    __half ll = __float2half_rn(r);
    h = __half_as_ushort(hh); l = __half_as_ushort(ll);
}

// one k16 step for a 24-col quarter: 9 bf16 MMAs (hh, hl, lh), B frags passed in
__device__ __forceinline__ void kt_mma(float (&acc)[3][4],
        u32 ah0,u32 ah1,u32 ah2,u32 ah3,
        u32 al0,u32 al1,u32 al2,u32 al3,
        u32 h0,u32 h1,u32 h2,u32 h3,u32 g0,u32 g1,
        u32 l0,u32 l1,u32 l2,u32 l3,u32 m0,u32 m1){
    MMA_BF16(acc[0], ah0,ah1,ah2,ah3, h0,h1);
    MMA_BF16(acc[1], ah0,ah1,ah2,ah3, h2,h3);
    MMA_BF16(acc[2], ah0,ah1,ah2,ah3, g0,g1);
    MMA_BF16(acc[0], ah0,ah1,ah2,ah3, l0,l1);
    MMA_BF16(acc[1], ah0,ah1,ah2,ah3, l2,l3);
    MMA_BF16(acc[2], ah0,ah1,ah2,ah3, m0,m1);
    MMA_BF16(acc[0], al0,al1,al2,al3, h0,h1);
    MMA_BF16(acc[1], al0,al1,al2,al3, h2,h3);
    MMA_BF16(acc[2], al0,al1,al2,al3, g0,g1);
}

// ---------------- prep: bias ----------------
__global__ void prep_bias(const float* __restrict__ qkv_w, const float* __restrict__ qkv_b,
                          const float* __restrict__ gam, const float* __restrict__ bet,
                          const float* __restrict__ mn,  const float* __restrict__ vr){
    int o = blockIdx.x;
    int c = threadIdx.x;
    __shared__ float red[CC];
    float inv   = gam[c] * rsqrtf(vr[c] + 1e-5f);
    float shift = bet[c] - mn[c]*inv;
    red[c] = qkv_w[o*CC + c] * shift;
    __syncthreads();
    if (c < 32){
        float s = red[c] + red[c+32] + red[c+64];
        #pragma unroll
        for (int off = 16; off; off >>= 1) s += __shfl_down_sync(0xffffffffu, s, off);
        if (c == 0) g_bias[o] = s + qkv_b[o];
    }
}

// ---------------- prep: W' in A-fragment order ----------------
__global__ void prep_frag(const float* __restrict__ qkv_w,
                          const float* __restrict__ gam, const float* __restrict__ vr){
    int blk = blockIdx.x;          // 108 = p*36 + mt*6 + kt
    int p  = blk / 36;
    int mt = (blk / 6) % 6;
    int kt = blk % 6;
    int lane = threadIdx.x;
    int r  = lane >> 2;
    int c0 = 2*(lane & 3);
    int base = (blk*32 + lane)*4;
    #pragma unroll
    for (int q = 0; q < 4; ++q){
        int ro = mt*16 + r + (q & 1)*8;
        int co = kt*16 + c0 + (q >> 1)*8;
        float inv0 = gam[co]   * rsqrtf(vr[co]   + 1e-5f);
        float inv1 = gam[co+1] * rsqrtf(vr[co+1] + 1e-5f);
        u16 h0,l0,h1,l1;
        split2(qkv_w[(p*CC + ro)*CC + co]   * inv0, h0, l0);
        split2(qkv_w[(p*CC + ro)*CC + co+1] * inv1, h1, l1);
        g_WfragH[base + q] = (u32)h0 | ((u32)h1 << 16);
        g_WfragL[base + q] = (u32)l0 | ((u32)l1 << 16);
    }
}

// ---------------- fused attention kernel (persistent, prefetch, reg-softmax, fp16 AV) ----------------
__global__ __launch_bounds__(NT) void attn_kernel(const float* __restrict__ x,
                                                  float* __restrict__ out){
    extern __shared__ char smc[];
    const int t    = threadIdx.x;
    const int lane = t & 31;
    const int warp = t >> 5;     // 0..23
    const int mt = warp >> 2;    // 0..5
    const int nq = warp & 3;     // 0..3
    const int g  = lane >> 2;    // 0..7
    const int tq = lane & 3;     // 0..3

    const int ai = lane >> 3, ar = lane & 7;
    const u32 aOff = (u32)((mt*16 + (ai&1)*8 + ar)*PL + ((ai>>1)*8)*2);
    const u32 bRow  = (u32)(((lane & 7) + ((lane >> 3) & 1)*8)*PL);
    const u32 bOff4 = bRow + (u32)(nq*48 + ((lane >> 4)&1)*16);
    const u32 bOff2 = (u32)((((lane & 15) & 7) + (((lane & 15) >> 3))*8)*PL) + (u32)(nq*48 + 32);

    const u32 sb = smem_u32(smc);
    const int qw0 = mt*16 + g;

    // ---- prefetch first row into XSTAGE ----
    {
        const int bh0 = blockIdx.x;
        const size_t basep = (size_t)(bh0 >> 9)*CC*HWX + (size_t)(bh0 & 511)*WW;
        for (int idx = t; idx < CC*24; idx += NT){
            int c = idx/24, j = idx%24;
            cp_async16(sb + O_XST + (u32)idx*16, x + basep + (size_t)c*HWX + 4*j);
        }
        CP_COMMIT();
    }

    for (int bh = blockIdx.x; bh < NROWS; bh += GRID){
        const size_t base = (size_t)(bh >> 9)*CC*HWX + (size_t)(bh & 511)*WW;

        // ---- consume staged x: split into XB planes [c][w] ----
        CP_WAIT0();
        for (int idx = t; idx < CC*24; idx += NT){
            int c = idx/24, j = idx%24;
            float4 v = *(const float4*)(smc + O_XST + idx*16);
            u16 hh[4], ll[4];
            split2(v.x, hh[0], ll[0]); split2(v.y, hh[1], ll[1]);
            split2(v.z, hh[2], ll[2]); split2(v.w, hh[3], ll[3]);
            u32 off = (u32)(c*PL + 8*j);
            *(u32*)(smc + O_XBH + off)     = (u32)hh[0] | ((u32)hh[1] << 16);
            *(u32*)(smc + O_XBH + off + 4) = (u32)hh[2] | ((u32)hh[3] << 16);
            *(u32*)(smc + O_XBL + off)     = (u32)ll[0] | ((u32)ll[1] << 16);
            *(u32*)(smc + O_XBL + off + 4) = (u32)ll[2] | ((u32)ll[3] << 16);
        }
        __syncthreads();   // (1) XB visible

        // ---- QKV: kt-outer, pass-inner; B fragments loaded ONCE per kt ----
        {
            float acc3[3][3][4];
            #pragma unroll
            for (int p = 0; p < 3; ++p){
                float bg  = g_bias[p*CC + qw0];
                float bg8 = g_bias[p*CC + qw0 + 8];
                #pragma unroll
                for (int n6 = 0; n6 < 3; ++n6){
                    acc3[p][n6][0] = bg;  acc3[p][n6][1] = bg;
                    acc3[p][n6][2] = bg8; acc3[p][n6][3] = bg8;
                }
            }
            const u32* WfH = g_WfragH + (mt*6)*128 + lane*4;
            const u32* WfL = g_WfragL + (mt*6)*128 + lane*4;

            #pragma unroll
            for (int kt = 0; kt < 6; ++kt){
                u32 h0,h1,h2,h3, g0,g1, l0,l1,l2,l3, m0,m1;
                LDSM4T(h0,h1,h2,h3, sb + O_XBH + bOff4 + (u32)(kt*16*PL));
                LDSM2T(g0,g1,       sb + O_XBH + bOff2 + (u32)(kt*16*PL));
                LDSM4T(l0,l1,l2,l3, sb + O_XBL + bOff4 + (u32)(kt*16*PL));
                LDSM2T(m0,m1,       sb + O_XBL + bOff2 + (u32)(kt*16*PL));
                #pragma unroll
                for (int p = 0; p < 3; ++p){
                    uint4 AH = *(const uint4*)(WfH + (p*36 + kt)*128);
                    uint4 AL = *(const uint4*)(WfL + (p*36 + kt)*128);
                    kt_mma(acc3[p], AH.x,AH.y,AH.z,AH.w, AL.x,AL.y,AL.z,AL.w,
                           h0,h1,h2,h3,g0,g1, l0,l1,l2,l3,m0,m1);
                }
            }

            // epilogues -> split planes (q,k: bf16 3-split layout; v: fp16 2-split)
            #pragma unroll
            for (int p = 0; p < 3; ++p){
                #pragma unroll
                for (int n6 = 0; n6 < 3; ++n6){
                    int w0 = nq*24 + n6*8 + 2*tq;
                    int o0 = qw0;
                    u16 h0,l0;
                    if (p == 1){
                        u16 h1,l1;
                        split2(acc3[p][n6][0], h0, l0); split2(acc3[p][n6][1], h1, l1);
                        *(u32*)(smc + O_KH + o0*PL + w0*2) = (u32)h0 | ((u32)h1 << 16);
                        *(u32*)(smc + O_KL + o0*PL + w0*2) = (u32)l0 | ((u32)l1 << 16);
                        split2(acc3[p][n6][2], h0, l0); split2(acc3[p][n6][3], h1, l1);
                        *(u32*)(smc + O_KH + (o0+8)*PL + w0*2) = (u32)h0 | ((u32)h1 << 16);
                        *(u32*)(smc + O_KL + (o0+8)*PL + w0*2) = (u32)l0 | ((u32)l1 << 16);
                    } else if (p == 0){
                        split2(acc3[p][n6][0], h0, l0);
                        *(u16*)(smc + O_QTH + (w0  )*PL + o0*2) = h0;
                        *(u16*)(smc + O_QTL + (w0  )*PL + o0*2) = l0;
                        split2(acc3[p][n6][1], h0, l0);
                        *(u16*)(smc + O_QTH + (w0+1)*PL + o0*2) = h0;
                        *(u16*)(smc + O_QTL + (w0+1)*PL + o0*2) = l0;
                        split2(acc3[p][n6][2], h0, l0);
                        *(u16*)(smc + O_QTH + (w0  )*PL + (o0+8)*2) = h0;
                        *(u16*)(smc + O_QTL + (w0  )*PL + (o0+8)*2) = l0;
                        split2(acc3[p][n6][3], h0, l0);
                        *(u16*)(smc + O_QTH + (w0+1)*PL + (o0+8)*2) = h0;
                        *(u16*)(smc + O_QTL + (w0+1)*PL + (o0+8)*2) = l0;
                    } else {
                        // v: fp16 2-split, transposed [w][o]
                        split2h(acc3[p][n6][0], h0, l0);
                        *(u16*)(smc + O_VTH + (w0  )*PL + o0*2) = h0;
                        *(u16*)(smc + O_VTL + (w0  )*PL + o0*2) = l0;
                        split2h(acc3[p][n6][1], h0, l0);
                        *(u16*)(smc + O_VTH + (w0+1)*PL + o0*2) = h0;
                        *(u16*)(smc + O_VTL + (w0+1)*PL + o0*2) = l0;
                        split2h(acc3[p][n6][2], h0, l0);
                        *(u16*)(smc + O_VTH + (w0  )*PL + (o0+8)*2) = h0;
                        *(u16*)(smc + O_VTL + (w0  )*PL + (o0+8)*2) = l0;
                        split2h(acc3[p][n6][3], h0, l0);
                        *(u16*)(smc + O_VTH + (w0+1)*PL + (o0+8)*2) = h0;
                        *(u16*)(smc + O_VTL + (w0+1)*PL + (o0+8)*2) = l0;
                    }
                }
            }
        }
        __syncthreads();   // (2) qT, k, vT visible; XSTAGE reads done

        // ---- prefetch next row into XSTAGE (hidden behind score/softmax/AV) ----
        {
            int nxt = bh + GRID;
            if (nxt < NROWS){
                const size_t basep = (size_t)(nxt >> 9)*CC*HWX + (size_t)(nxt & 511)*WW;
                for (int idx = t; idx < CC*24; idx += NT){
                    int c = idx/24, j = idx%24;
                    cp_async16(sb + O_XST + (u32)idx*16, x + basep + (size_t)c*HWX + 4*j);
                }
                CP_COMMIT();
            }
        }

        float acc[3][4];

        // ---- score: A=qT (smem), B=k; result stays in registers ----
        #pragma unroll
        for (int n6 = 0; n6 < 3; ++n6){
            acc[n6][0]=0.f; acc[n6][1]=0.f; acc[n6][2]=0.f; acc[n6][3]=0.f;
        }
        #pragma unroll
        for (int kt = 0; kt < 6; ++kt){
            u32 ah0,ah1,ah2,ah3, al0,al1,al2,al3;
            u32 h0,h1,h2,h3, g0,g1, l0,l1,l2,l3, m0,m1;
            LDSM4(ah0,ah1,ah2,ah3, sb + O_QTH + aOff + kt*32);
            LDSM4(al0,al1,al2,al3, sb + O_QTL + aOff + kt*32);
            LDSM4T(h0,h1,h2,h3, sb + O_KH + bOff4 + (u32)(kt*16*PL));
            LDSM2T(g0,g1,       sb + O_KH + bOff2 + (u32)(kt*16*PL));
            LDSM4T(l0,l1,l2,l3, sb + O_KL + bOff4 + (u32)(kt*16*PL));
            LDSM2T(m0,m1,       sb + O_KL + bOff2 + (u32)(kt*16*PL));
            kt_mma(acc, ah0,ah1,ah2,ah3, al0,al1,al2,al3,
                   h0,h1,h2,h3,g0,g1, l0,l1,l2,l3,m0,m1);
        }

        // ---- register softmax, stage 1: per-warp partials over 24 kw cols ----
        float eA[6], eB[6], mA, mB, sA, sB;
        {
            mA = fmaxf(fmaxf(fmaxf(acc[0][0],acc[0][1]), fmaxf(acc[1][0],acc[1][1])),
                       fmaxf(acc[2][0],acc[2][1]));
            mB = fmaxf(fmaxf(fmaxf(acc[0][2],acc[0][3]), fmaxf(acc[1][2],acc[1][3])),
                       fmaxf(acc[2][2],acc[2][3]));
            mA = fmaxf(mA, __shfl_xor_sync(0xffffffffu, mA, 1));
            mA = fmaxf(mA, __shfl_xor_sync(0xffffffffu, mA, 2));
            mB = fmaxf(mB, __shfl_xor_sync(0xffffffffu, mB, 1));
            mB = fmaxf(mB, __shfl_xor_sync(0xffffffffu, mB, 2));
            sA = 0.f; sB = 0.f;
            #pragma unroll
            for (int n6 = 0; n6 < 3; ++n6){
                eA[2*n6  ] = __expf(acc[n6][0] - mA); sA += eA[2*n6  ];
                eA[2*n6+1] = __expf(acc[n6][1] - mA); sA += eA[2*n6+1];
                eB[2*n6  ] = __expf(acc[n6][2] - mB); sB += eB[2*n6  ];
                eB[2*n6+1] = __expf(acc[n6][3] - mB); sB += eB[2*n6+1];
            }
            sA += __shfl_xor_sync(0xffffffffu, sA, 1);
            sA += __shfl_xor_sync(0xffffffffu, sA, 2);
            sB += __shfl_xor_sync(0xffffffffu, sB, 1);
            sB += __shfl_xor_sync(0xffffffffu, sB, 2);
            if (tq == 0){
                *(float2*)(smc + O_PM + (qw0  )*32 + nq*8) = make_float2(mA, sA);
                *(float2*)(smc + O_PM + (qw0+8)*32 + nq*8) = make_float2(mB, sB);
            }
        }
        __syncthreads();   // (3) partials visible; ALL qT/K reads done CTA-wide

        // ---- softmax stage 2: combine, write single fp16 attn plane into K area ----
        {
            float4 a0 = *(const float4*)(smc + O_PM + (qw0  )*32);
            float4 a1 = *(const float4*)(smc + O_PM + (qw0  )*32 + 16);
            float4 b0 = *(const float4*)(smc + O_PM + (qw0+8)*32);
            float4 b1 = *(const float4*)(smc + O_PM + (qw0+8)*32 + 16);
            float MA = fmaxf(fmaxf(a0.x, a0.z), fmaxf(a1.x, a1.z));
            float MB = fmaxf(fmaxf(b0.x, b0.z), fmaxf(b1.x, b1.z));
            float SA = a0.y*__expf(a0.x-MA) + a0.w*__expf(a0.z-MA)
                     + a1.y*__expf(a1.x-MA) + a1.w*__expf(a1.z-MA);
            float SB = b0.y*__expf(b0.x-MB) + b0.w*__expf(b0.z-MB)
                     + b1.y*__expf(b1.x-MB) + b1.w*__expf(b1.z-MB);
            float fA = __expf(mA - MA) / SA;
            float fB = __expf(mB - MB) / SB;
            #pragma unroll
            for (int n6 = 0; n6 < 3; ++n6){
                int kw0 = nq*24 + n6*8 + 2*tq;
                __half2 pa = __floats2half2_rn(eA[2*n6]*fA, eA[2*n6+1]*fA);
                __half2 pb = __floats2half2_rn(eB[2*n6]*fB, eB[2*n6+1]*fB);
                *(u32*)(smc + O_ATH + (qw0  )*PL + kw0*2) = *(u32*)&pa;
                *(u32*)(smc + O_ATH + (qw0+8)*PL + kw0*2) = *(u32*)&pb;
            }
        }
        NBAR(mt + 1);      // (4) attn rows [16mt,16mt+16) complete within mt-group

        // ---- AV (fp16, 2-product): A=attn single plane, B=vT hi/lo ----
        #pragma unroll
        for (int n6 = 0; n6 < 3; ++n6){
            acc[n6][0]=0.f; acc[n6][1]=0.f; acc[n6][2]=0.f; acc[n6][3]=0.f;
        }
        #pragma unroll
        for (int kt = 0; kt < 6; ++kt){
            u32 ah0,ah1,ah2,ah3;
            u32 h0,h1,h2,h3, g0,g1, l0,l1,l2,l3, m0,m1;
            LDSM4(ah0,ah1,ah2,ah3, sb + O_ATH + aOff + kt*32);
            LDSM4T(h0,h1,h2,h3, sb + O_VTH + bOff4 + (u32)(kt*16*PL));
            LDSM2T(g0,g1,       sb + O_VTH + bOff2 + (u32)(kt*16*PL));
            LDSM4T(l0,l1,l2,l3, sb + O_VTL + bOff4 + (u32)(kt*16*PL));
            LDSM2T(m0,m1,       sb + O_VTL + bOff2 + (u32)(kt*16*PL));
            MMA_F16(acc[0], ah0,ah1,ah2,ah3, h0,h1);
            MMA_F16(acc[1], ah0,ah1,ah2,ah3, h2,h3);
            MMA_F16(acc[2], ah0,ah1,ah2,ah3, g0,g1);
            MMA_F16(acc[0], ah0,ah1,ah2,ah3, l0,l1);
            MMA_F16(acc[1], ah0,ah1,ah2,ah3, l2,l3);
            MMA_F16(acc[2], ah0,ah1,ah2,ah3, m0,m1);
        }
        {
            float* of = (float*)(smc + O_OF);
            #pragma unroll
            for (int n6 = 0; n6 < 3; ++n6){
                int c0 = nq*24 + n6*8 + 2*tq;
                of[(c0  )*100 + qw0    ] = acc[n6][0];
                of[(c0+1)*100 + qw0    ] = acc[n6][1];
                of[(c0  )*100 + qw0 + 8] = acc[n6][2];
                of[(c0+1)*100 + qw0 + 8] = acc[n6][3];
            }
        }
        __syncthreads();   // (5) out staging visible

        // ---- residual from XB planes (x ≈ hi+lo) + coalesced writeout ----
        {
            const float* of = (const float*)(smc + O_OF);
            for (int idx = t; idx < CC*24; idx += NT){
                int c = idx/24, j = idx%24;
                float4 ov = *(const float4*)(of + c*100 + 4*j);
                u32 off = (u32)(c*PL + 8*j);
                __nv_bfloat162 h01 = *(__nv_bfloat162*)(smc + O_XBH + off);
                __nv_bfloat162 h23 = *(__nv_bfloat162*)(smc + O_XBH + off + 4);
                __nv_bfloat162 l01 = *(__nv_bfloat162*)(smc + O_XBL + off);
                __nv_bfloat162 l23 = *(__nv_bfloat162*)(smc + O_XBL + off + 4);
                float2 fh01 = __bfloat1622float2(h01);
                float2 fh23 = __bfloat1622float2(h23);
                float2 fl01 = __bfloat1622float2(l01);
                float2 fl23 = __bfloat1622float2(l23);
                ov.x += fh01.x + fl01.x;
                ov.y += fh01.y + fl01.y;
                ov.z += fh23.x + fl23.x;
                ov.w += fh23.y + fl23.y;
                *(float4*)(out + base + (size_t)c*HWX + 4*j) = ov;
            }
        }
        __syncthreads();   // (6) row done; planes reusable next iteration
    }
}

extern "C" void kernel_launch(void* const* d_in, const int* in_sizes, int n_in,
                              void* d_out, int out_size){
    const float* x     = (const float*)d_in[0];
    const float* gam   = (const float*)d_in[1];
    const float* bet   = (const float*)d_in[2];
    const float* mn    = (const float*)d_in[3];
    const float* vr    = (const float*)d_in[4];
    const float* qkv_w = (const float*)d_in[5];
    const float* qkv_b = (const float*)d_in[6];
    float* out = (float*)d_out;

    cudaFuncSetAttribute(attn_kernel, cudaFuncAttributeMaxDynamicSharedMemorySize, SMEM_BYTES);

    prep_bias<<<OC, CC>>>(qkv_w, qkv_b, gam, bet, mn, vr);
    prep_frag<<<108, 32>>>(qkv_w, gam, vr);
    attn_kernel<<<GRID, NT, SMEM_BYTES>>>(x, out);
}

// round 16
// speedup vs baseline: 4.3860x; 1.0641x over previous
#include <cuda_runtime.h>
#include <cuda_bf16.h>
#include <cuda_fp16.h>
#include <cstdint>

#define BB 8
#define CC 96
#define HH 512
#define WW 96
#define HWX (HH*WW)     // 49152
#define OC  288
#define NT  768         // 24 warps
#define NROWS (BB*HH)   // 4096
#define GRID 152        // persistent: one CTA per SM

typedef unsigned int u32;
typedef unsigned short u16;

// prep outputs: W' (BN folded) in EXACT mma A-fragment order, hi/lo bf16 planes
__device__ u32   g_WfragH[108*32*4];
__device__ u32   g_WfragL[108*32*4];
__device__ float g_bias[OC];

// ---- smem map (bytes). 16-bit planes: 96 rows x 104 elems (stride 208B) ----
#define PL   208
#define PLSZ (96*PL)        // 19968
#define O_XBH 0             // x split hi [c][w] (B for QKV; residual source)
#define O_XBL (PLSZ)
#define O_QTH (2*PLSZ)      // qT hi [w][c]  (A for score)
#define O_QTL (3*PLSZ)
#define O_OF  (2*PLSZ)      // out f32 [c][w] stride 100 (qT area, dead after score)
#define O_KH  (4*PLSZ)      // k hi [c][w]   (B for score)
#define O_KL  (5*PLSZ)
#define O_ATH (4*PLSZ)      // attn fp16 [qw][kw] (K area, safe after barrier 3)
#define O_VTH (6*PLSZ)      // vT fp16 single plane [w][c]  (B for AV)
#define O_VTL (7*PLSZ)      // (unused this round; kept for layout stability)
#define O_PM  (8*PLSZ)      // softmax partials [96][4] float2 = 3072 B
#define O_XST (8*PLSZ + 3072)  // next-row x staging (raw f32): 36864 B
#define SMEM_BYTES (O_XST + 36864)   // 199680

__device__ __forceinline__ u32 smem_u32(const void* p){
    u32 a; asm("{ .reg .u64 t; cvta.to.shared.u64 t, %1; cvt.u32.u64 %0, t; }" : "=r"(a) : "l"(p));
    return a;
}
#define LDSM4(r0,r1,r2,r3,addr) \
    asm volatile("ldmatrix.sync.aligned.m8n8.x4.shared.b16 {%0,%1,%2,%3}, [%4];" \
        : "=r"(r0),"=r"(r1),"=r"(r2),"=r"(r3) : "r"(addr))
#define LDSM4T(r0,r1,r2,r3,addr) \
    asm volatile("ldmatrix.sync.aligned.m8n8.x4.trans.shared.b16 {%0,%1,%2,%3}, [%4];" \
        : "=r"(r0),"=r"(r1),"=r"(r2),"=r"(r3) : "r"(addr))
#define LDSM2T(r0,r1,addr) \
    asm volatile("ldmatrix.sync.aligned.m8n8.x2.trans.shared.b16 {%0,%1}, [%2];" \
        : "=r"(r0),"=r"(r1) : "r"(addr))
#define MMA_BF16(d,a0,a1,a2,a3,b0,b1) \
    asm volatile("mma.sync.aligned.m16n8k16.row.col.f32.bf16.bf16.f32 " \
        "{%0,%1,%2,%3},{%4,%5,%6,%7},{%8,%9},{%0,%1,%2,%3};" \
        : "+f"((d)[0]),"+f"((d)[1]),"+f"((d)[2]),"+f"((d)[3]) \
        : "r"(a0),"r"(a1),"r"(a2),"r"(a3),"r"(b0),"r"(b1))
#define MMA_F16(d,a0,a1,a2,a3,b0,b1) \
    asm volatile("mma.sync.aligned.m16n8k16.row.col.f32.f16.f16.f32 " \
        "{%0,%1,%2,%3},{%4,%5,%6,%7},{%8,%9},{%0,%1,%2,%3};" \
        : "+f"((d)[0]),"+f"((d)[1]),"+f"((d)[2]),"+f"((d)[3]) \
        : "r"(a0),"r"(a1),"r"(a2),"r"(a3),"r"(b0),"r"(b1))
#define NBAR(id) asm volatile("bar.sync %0, 128;" :: "r"(id) : "memory")
__device__ __forceinline__ void cp_async16(u32 dst, const void* src){
    asm volatile("cp.async.cg.shared.global [%0], [%1], 16;" :: "r"(dst), "l"(src));
}
#define CP_COMMIT() asm volatile("cp.async.commit_group;" ::: "memory")
#define CP_WAIT0()  asm volatile("cp.async.wait_group 0;" ::: "memory")

__device__ __forceinline__ void split2(float f, u16& h, u16& l){
    __nv_bfloat16 bh = __float2bfloat16_rn(f);
    float r = f - __bfloat162float(bh);
    __nv_bfloat16 bl = __float2bfloat16_rn(r);
    h = __bfloat16_as_ushort(bh); l = __bfloat16_as_ushort(bl);
}

// one k16 step for a 24-col quarter: 9 bf16 MMAs (hh, hl, lh), B frags passed in
__device__ __forceinline__ void kt_mma(float (&acc)[3][4],
        u32 ah0,u32 ah1,u32 ah2,u32 ah3,
        u32 al0,u32 al1,u32 al2,u32 al3,
        u32 h0,u32 h1,u32 h2,u32 h3,u32 g0,u32 g1,
        u32 l0,u32 l1,u32 l2,u32 l3,u32 m0,u32 m1){
    MMA_BF16(acc[0], ah0,ah1,ah2,ah3, h0,h1);
    MMA_BF16(acc[1], ah0,ah1,ah2,ah3, h2,h3);
    MMA_BF16(acc[2], ah0,ah1,ah2,ah3, g0,g1);
    MMA_BF16(acc[0], ah0,ah1,ah2,ah3, l0,l1);
    MMA_BF16(acc[1], ah0,ah1,ah2,ah3, l2,l3);
    MMA_BF16(acc[2], ah0,ah1,ah2,ah3, m0,m1);
    MMA_BF16(acc[0], al0,al1,al2,al3, h0,h1);
    MMA_BF16(acc[1], al0,al1,al2,al3, h2,h3);
    MMA_BF16(acc[2], al0,al1,al2,al3, g0,g1);
}

// ---------------- prep: bias ----------------
__global__ void prep_bias(const float* __restrict__ qkv_w, const float* __restrict__ qkv_b,
                          const float* __restrict__ gam, const float* __restrict__ bet,
                          const float* __restrict__ mn,  const float* __restrict__ vr){
    int o = blockIdx.x;
    int c = threadIdx.x;
    __shared__ float red[CC];
    float inv   = gam[c] * rsqrtf(vr[c] + 1e-5f);
    float shift = bet[c] - mn[c]*inv;
    red[c] = qkv_w[o*CC + c] * shift;
    __syncthreads();
    if (c < 32){
        float s = red[c] + red[c+32] + red[c+64];
        #pragma unroll
        for (int off = 16; off; off >>= 1) s += __shfl_down_sync(0xffffffffu, s, off);
        if (c == 0) g_bias[o] = s + qkv_b[o];
    }
}

// ---------------- prep: W' in A-fragment order ----------------
__global__ void prep_frag(const float* __restrict__ qkv_w,
                          const float* __restrict__ gam, const float* __restrict__ vr){
    int blk = blockIdx.x;          // 108 = p*36 + mt*6 + kt
    int p  = blk / 36;
    int mt = (blk / 6) % 6;
    int kt = blk % 6;
    int lane = threadIdx.x;
    int r  = lane >> 2;
    int c0 = 2*(lane & 3);
    int base = (blk*32 + lane)*4;
    #pragma unroll
    for (int q = 0; q < 4; ++q){
        int ro = mt*16 + r + (q & 1)*8;
        int co = kt*16 + c0 + (q >> 1)*8;
        float inv0 = gam[co]   * rsqrtf(vr[co]   + 1e-5f);
        float inv1 = gam[co+1] * rsqrtf(vr[co+1] + 1e-5f);
        u16 h0,l0,h1,l1;
        split2(qkv_w[(p*CC + ro)*CC + co]   * inv0, h0, l0);
        split2(qkv_w[(p*CC + ro)*CC + co+1] * inv1, h1, l1);
        g_WfragH[base + q] = (u32)h0 | ((u32)h1 << 16);
        g_WfragL[base + q] = (u32)l0 | ((u32)l1 << 16);
    }
}

// ---------------- fused attention kernel ----------------
__global__ __launch_bounds__(NT) void attn_kernel(const float* __restrict__ x,
                                                  float* __restrict__ out){
    extern __shared__ char smc[];
    const int t    = threadIdx.x;
    const int lane = t & 31;
    const int warp = t >> 5;     // 0..23
    const int mt = warp >> 2;    // 0..5
    const int nq = warp & 3;     // 0..3
    const int g  = lane >> 2;    // 0..7
    const int tq = lane & 3;     // 0..3

    const int ai = lane >> 3, ar = lane & 7;
    const u32 aOff = (u32)((mt*16 + (ai&1)*8 + ar)*PL + ((ai>>1)*8)*2);
    const u32 bRow  = (u32)(((lane & 7) + ((lane >> 3) & 1)*8)*PL);
    const u32 bOff4 = bRow + (u32)(nq*48 + ((lane >> 4)&1)*16);
    const u32 bOff2 = (u32)((((lane & 15) & 7) + (((lane & 15) >> 3))*8)*PL) + (u32)(nq*48 + 32);

    const u32 sb = smem_u32(smc);
    const int qw0 = mt*16 + g;

    // ---- prefetch first row into XSTAGE ----
    {
        const int bh0 = blockIdx.x;
        const size_t basep = (size_t)(bh0 >> 9)*CC*HWX + (size_t)(bh0 & 511)*WW;
        for (int idx = t; idx < CC*24; idx += NT){
            int c = idx/24, j = idx%24;
            cp_async16(sb + O_XST + (u32)idx*16, x + basep + (size_t)c*HWX + 4*j);
        }
        CP_COMMIT();
    }

    for (int bh = blockIdx.x; bh < NROWS; bh += GRID){
        const size_t base = (size_t)(bh >> 9)*CC*HWX + (size_t)(bh & 511)*WW;

        // ---- consume staged x: split into XB planes [c][w] ----
        CP_WAIT0();
        for (int idx = t; idx < CC*24; idx += NT){
            int c = idx/24, j = idx%24;
            float4 v = *(const float4*)(smc + O_XST + idx*16);
            u16 hh[4], ll[4];
            split2(v.x, hh[0], ll[0]); split2(v.y, hh[1], ll[1]);
            split2(v.z, hh[2], ll[2]); split2(v.w, hh[3], ll[3]);
            u32 off = (u32)(c*PL + 8*j);
            *(u32*)(smc + O_XBH + off)     = (u32)hh[0] | ((u32)hh[1] << 16);
            *(u32*)(smc + O_XBH + off + 4) = (u32)hh[2] | ((u32)hh[3] << 16);
            *(u32*)(smc + O_XBL + off)     = (u32)ll[0] | ((u32)ll[1] << 16);
            *(u32*)(smc + O_XBL + off + 4) = (u32)ll[2] | ((u32)ll[3] << 16);
        }
        __syncthreads();   // (1) XB visible

        // ---- QKV: kt-outer, pass-inner; B fragments loaded ONCE per kt ----
        {
            float acc3[3][3][4];
            #pragma unroll
            for (int p = 0; p < 3; ++p){
                float bg  = g_bias[p*CC + qw0];
                float bg8 = g_bias[p*CC + qw0 + 8];
                #pragma unroll
                for (int n6 = 0; n6 < 3; ++n6){
                    acc3[p][n6][0] = bg;  acc3[p][n6][1] = bg;
                    acc3[p][n6][2] = bg8; acc3[p][n6][3] = bg8;
                }
            }
            const u32* WfH = g_WfragH + (mt*6)*128 + lane*4;
            const u32* WfL = g_WfragL + (mt*6)*128 + lane*4;

            #pragma unroll
            for (int kt = 0; kt < 6; ++kt){
                u32 h0,h1,h2,h3, g0,g1, l0,l1,l2,l3, m0,m1;
                LDSM4T(h0,h1,h2,h3, sb + O_XBH + bOff4 + (u32)(kt*16*PL));
                LDSM2T(g0,g1,       sb + O_XBH + bOff2 + (u32)(kt*16*PL));
                LDSM4T(l0,l1,l2,l3, sb + O_XBL + bOff4 + (u32)(kt*16*PL));
                LDSM2T(m0,m1,       sb + O_XBL + bOff2 + (u32)(kt*16*PL));
                #pragma unroll
                for (int p = 0; p < 3; ++p){
                    uint4 AH = *(const uint4*)(WfH + (p*36 + kt)*128);
                    uint4 AL = *(const uint4*)(WfL + (p*36 + kt)*128);
                    kt_mma(acc3[p], AH.x,AH.y,AH.z,AH.w, AL.x,AL.y,AL.z,AL.w,
                           h0,h1,h2,h3,g0,g1, l0,l1,l2,l3,m0,m1);
                }
            }

            // epilogues: q,k bf16 hi/lo; v single fp16 plane (transposed)
            #pragma unroll
            for (int p = 0; p < 3; ++p){
                #pragma unroll
                for (int n6 = 0; n6 < 3; ++n6){
                    int w0 = nq*24 + n6*8 + 2*tq;
                    int o0 = qw0;
                    u16 h0,l0;
                    if (p == 1){
                        u16 h1,l1;
                        split2(acc3[p][n6][0], h0, l0); split2(acc3[p][n6][1], h1, l1);
                        *(u32*)(smc + O_KH + o0*PL + w0*2) = (u32)h0 | ((u32)h1 << 16);
                        *(u32*)(smc + O_KL + o0*PL + w0*2) = (u32)l0 | ((u32)l1 << 16);
                        split2(acc3[p][n6][2], h0, l0); split2(acc3[p][n6][3], h1, l1);
                        *(u32*)(smc + O_KH + (o0+8)*PL + w0*2) = (u32)h0 | ((u32)h1 << 16);
                        *(u32*)(smc + O_KL + (o0+8)*PL + w0*2) = (u32)l0 | ((u32)l1 << 16);
                    } else if (p == 0){
                        split2(acc3[p][n6][0], h0, l0);
                        *(u16*)(smc + O_QTH + (w0  )*PL + o0*2) = h0;
                        *(u16*)(smc + O_QTL + (w0  )*PL + o0*2) = l0;
                        split2(acc3[p][n6][1], h0, l0);
                        *(u16*)(smc + O_QTH + (w0+1)*PL + o0*2) = h0;
                        *(u16*)(smc + O_QTL + (w0+1)*PL + o0*2) = l0;
                        split2(acc3[p][n6][2], h0, l0);
                        *(u16*)(smc + O_QTH + (w0  )*PL + (o0+8)*2) = h0;
                        *(u16*)(smc + O_QTL + (w0  )*PL + (o0+8)*2) = l0;
                        split2(acc3[p][n6][3], h0, l0);
                        *(u16*)(smc + O_QTH + (w0+1)*PL + (o0+8)*2) = h0;
                        *(u16*)(smc + O_QTL + (w0+1)*PL + (o0+8)*2) = l0;
                    } else {
                        // v: single fp16, transposed [w][o]
                        __half v0 = __float2half_rn(acc3[p][n6][0]);
                        __half v1 = __float2half_rn(acc3[p][n6][1]);
                        __half v2 = __float2half_rn(acc3[p][n6][2]);
                        __half v3 = __float2half_rn(acc3[p][n6][3]);
                        *(u16*)(smc + O_VTH + (w0  )*PL + o0*2) = __half_as_ushort(v0);
                        *(u16*)(smc + O_VTH + (w0+1)*PL + o0*2) = __half_as_ushort(v1);
                        *(u16*)(smc + O_VTH + (w0  )*PL + (o0+8)*2) = __half_as_ushort(v2);
                        *(u16*)(smc + O_VTH + (w0+1)*PL + (o0+8)*2) = __half_as_ushort(v3);
                    }
                }
            }
        }
        __syncthreads();   // (2) qT, k, vT visible; XSTAGE reads done

        // ---- prefetch next row into XSTAGE (hidden behind score/softmax/AV) ----
        {
            int nxt = bh + GRID;
            if (nxt < NROWS){
                const size_t basep = (size_t)(nxt >> 9)*CC*HWX + (size_t)(nxt & 511)*WW;
                for (int idx = t; idx < CC*24; idx += NT){
                    int c = idx/24, j = idx%24;
                    cp_async16(sb + O_XST + (u32)idx*16, x + basep + (size_t)c*HWX + 4*j);
                }
                CP_COMMIT();
            }
        }

        float acc[3][4];

        // ---- score: A=qT (smem), B=k; result stays in registers ----
        #pragma unroll
        for (int n6 = 0; n6 < 3; ++n6){
            acc[n6][0]=0.f; acc[n6][1]=0.f; acc[n6][2]=0.f; acc[n6][3]=0.f;
        }
        #pragma unroll
        for (int kt = 0; kt < 6; ++kt){
            u32 ah0,ah1,ah2,ah3, al0,al1,al2,al3;
            u32 h0,h1,h2,h3, g0,g1, l0,l1,l2,l3, m0,m1;
            LDSM4(ah0,ah1,ah2,ah3, sb + O_QTH + aOff + kt*32);
            LDSM4(al0,al1,al2,al3, sb + O_QTL + aOff + kt*32);
            LDSM4T(h0,h1,h2,h3, sb + O_KH + bOff4 + (u32)(kt*16*PL));
            LDSM2T(g0,g1,       sb + O_KH + bOff2 + (u32)(kt*16*PL));
            LDSM4T(l0,l1,l2,l3, sb + O_KL + bOff4 + (u32)(kt*16*PL));
            LDSM2T(m0,m1,       sb + O_KL + bOff2 + (u32)(kt*16*PL));
            kt_mma(acc, ah0,ah1,ah2,ah3, al0,al1,al2,al3,
                   h0,h1,h2,h3,g0,g1, l0,l1,l2,l3,m0,m1);
        }

        // ---- register softmax, stage 1: per-warp partials over 24 kw cols ----
        float eA[6], eB[6], mA, mB, sA, sB;
        {
            mA = fmaxf(fmaxf(fmaxf(acc[0][0],acc[0][1]), fmaxf(acc[1][0],acc[1][1])),
                       fmaxf(acc[2][0],acc[2][1]));
            mB = fmaxf(fmaxf(fmaxf(acc[0][2],acc[0][3]), fmaxf(acc[1][2],acc[1][3])),
                       fmaxf(acc[2][2],acc[2][3]));
            mA = fmaxf(mA, __shfl_xor_sync(0xffffffffu, mA, 1));
            mA = fmaxf(mA, __shfl_xor_sync(0xffffffffu, mA, 2));
            mB = fmaxf(mB, __shfl_xor_sync(0xffffffffu, mB, 1));
            mB = fmaxf(mB, __shfl_xor_sync(0xffffffffu, mB, 2));
            sA = 0.f; sB = 0.f;
            #pragma unroll
            for (int n6 = 0; n6 < 3; ++n6){
                eA[2*n6  ] = __expf(acc[n6][0] - mA); sA += eA[2*n6  ];
                eA[2*n6+1] = __expf(acc[n6][1] - mA); sA += eA[2*n6+1];
                eB[2*n6  ] = __expf(acc[n6][2] - mB); sB += eB[2*n6  ];
                eB[2*n6+1] = __expf(acc[n6][3] - mB); sB += eB[2*n6+1];
            }
            sA += __shfl_xor_sync(0xffffffffu, sA, 1);
            sA += __shfl_xor_sync(0xffffffffu, sA, 2);
            sB += __shfl_xor_sync(0xffffffffu, sB, 1);
            sB += __shfl_xor_sync(0xffffffffu, sB, 2);
            if (tq == 0){
                *(float2*)(smc + O_PM + (qw0  )*32 + nq*8) = make_float2(mA, sA);
                *(float2*)(smc + O_PM + (qw0+8)*32 + nq*8) = make_float2(mB, sB);
            }
        }
        __syncthreads();   // (3) partials visible; ALL qT/K reads done CTA-wide

        // ---- softmax stage 2: combine, write single fp16 attn plane into K area ----
        {
            float4 a0 = *(const float4*)(smc + O_PM + (qw0  )*32);
            float4 a1 = *(const float4*)(smc + O_PM + (qw0  )*32 + 16);
            float4 b0 = *(const float4*)(smc + O_PM + (qw0+8)*32);
            float4 b1 = *(const float4*)(smc + O_PM + (qw0+8)*32 + 16);
            float MA = fmaxf(fmaxf(a0.x, a0.z), fmaxf(a1.x, a1.z));
            float MB = fmaxf(fmaxf(b0.x, b0.z), fmaxf(b1.x, b1.z));
            float SA = a0.y*__expf(a0.x-MA) + a0.w*__expf(a0.z-MA)
                     + a1.y*__expf(a1.x-MA) + a1.w*__expf(a1.z-MA);
            float SB = b0.y*__expf(b0.x-MB) + b0.w*__expf(b0.z-MB)
                     + b1.y*__expf(b1.x-MB) + b1.w*__expf(b1.z-MB);
            float fA = __expf(mA - MA) / SA;
            float fB = __expf(mB - MB) / SB;
            #pragma unroll
            for (int n6 = 0; n6 < 3; ++n6){
                int kw0 = nq*24 + n6*8 + 2*tq;
                __half2 pa = __floats2half2_rn(eA[2*n6]*fA, eA[2*n6+1]*fA);
                __half2 pb = __floats2half2_rn(eB[2*n6]*fB, eB[2*n6+1]*fB);
                *(u32*)(smc + O_ATH + (qw0  )*PL + kw0*2) = *(u32*)&pa;
                *(u32*)(smc + O_ATH + (qw0+8)*PL + kw0*2) = *(u32*)&pb;
            }
        }
        NBAR(mt + 1);      // (4) attn rows [16mt,16mt+16) complete within mt-group

        // ---- AV (fp16, 1-product): A=attn plane, B=vT plane ----
        #pragma unroll
        for (int n6 = 0; n6 < 3; ++n6){
            acc[n6][0]=0.f; acc[n6][1]=0.f; acc[n6][2]=0.f; acc[n6][3]=0.f;
        }
        #pragma unroll
        for (int kt = 0; kt < 6; ++kt){
            u32 ah0,ah1,ah2,ah3;
            u32 h0,h1,h2,h3, g0,g1;
            LDSM4(ah0,ah1,ah2,ah3, sb + O_ATH + aOff + kt*32);
            LDSM4T(h0,h1,h2,h3, sb + O_VTH + bOff4 + (u32)(kt*16*PL));
            LDSM2T(g0,g1,       sb + O_VTH + bOff2 + (u32)(kt*16*PL));
            MMA_F16(acc[0], ah0,ah1,ah2,ah3, h0,h1);
            MMA_F16(acc[1], ah0,ah1,ah2,ah3, h2,h3);
            MMA_F16(acc[2], ah0,ah1,ah2,ah3, g0,g1);
        }
        {
            float* of = (float*)(smc + O_OF);
            #pragma unroll
            for (int n6 = 0; n6 < 3; ++n6){
                int c0 = nq*24 + n6*8 + 2*tq;
                of[(c0  )*100 + qw0    ] = acc[n6][0];
                of[(c0+1)*100 + qw0    ] = acc[n6][1];
                of[(c0  )*100 + qw0 + 8] = acc[n6][2];
                of[(c0+1)*100 + qw0 + 8] = acc[n6][3];
            }
        }
        __syncthreads();   // (5) out staging visible

        // ---- residual from XB planes (x ≈ hi+lo) + coalesced writeout ----
        {
            const float* of = (const float*)(smc + O_OF);
            for (int idx = t; idx < CC*24; idx += NT){
                int c = idx/24, j = idx%24;
                float4 ov = *(const float4*)(of + c*100 + 4*j);
                u32 off = (u32)(c*PL + 8*j);
                __nv_bfloat162 h01 = *(__nv_bfloat162*)(smc + O_XBH + off);
                __nv_bfloat162 h23 = *(__nv_bfloat162*)(smc + O_XBH + off + 4);
                __nv_bfloat162 l01 = *(__nv_bfloat162*)(smc + O_XBL + off);
                __nv_bfloat162 l23 = *(__nv_bfloat162*)(smc + O_XBL + off + 4);
                float2 fh01 = __bfloat1622float2(h01);
                float2 fh23 = __bfloat1622float2(h23);
                float2 fl01 = __bfloat1622float2(l01);
                float2 fl23 = __bfloat1622float2(l23);
                ov.x += fh01.x + fl01.x;
                ov.y += fh01.y + fl01.y;
                ov.z += fh23.x + fl23.x;
                ov.w += fh23.y + fl23.y;
                *(float4*)(out + base + (size_t)c*HWX + 4*j) = ov;
            }
        }
        __syncthreads();   // (6) row done; planes reusable next iteration
    }
}

extern "C" void kernel_launch(void* const* d_in, const int* in_sizes, int n_in,
                              void* d_out, int out_size){
    const float* x     = (const float*)d_in[0];
    const float* gam   = (const float*)d_in[1];
    const float* bet   = (const float*)d_in[2];
    const float* mn    = (const float*)d_in[3];
    const float* vr    = (const float*)d_in[4];
    const float* qkv_w = (const float*)d_in[5];
    const float* qkv_b = (const float*)d_in[6];
    float* out = (float*)d_out;

    cudaFuncSetAttribute(attn_kernel, cudaFuncAttributeMaxDynamicSharedMemorySize, SMEM_BYTES);

    prep_bias<<<OC, CC>>>(qkv_w, qkv_b, gam, bet, mn, vr);
    prep_frag<<<108, 32>>>(qkv_w, gam, vr);
    attn_kernel<<<GRID, NT, SMEM_BYTES>>>(x, out);
}